// round 8
// baseline (speedup 1.0000x reference)
#include <cuda_runtime.h>
#include <cuda_bf16.h>
#include <cstdint>

#define N_NODES 60000
#define N_HERB  5000
#define NOUT2   25000
#define DIM     128
#define NREL    6
#define NB      30
#define NE      600000
#define NP      40000
#define NSEG1   (N_NODES * NREL)   // 360000
#define SCAN_BLK 1024
#define NBLK    ((NSEG1 + SCAN_BLK - 1) / SCAN_BLK)   // 352

// ---------------- scratch ----------------
__device__ float g_x1[(size_t)N_NODES * DIM];
__device__ float g_x2[(size_t)NOUT2 * DIM];
__device__ int   g_cnt[NSEG1];
__device__ int   g_off[NSEG1 + 1];
__device__ int   g_cursor[NSEG1];
__device__ int   g_esrc[NE];
__device__ int   g_bsum[NBLK], g_bpre[NBLK];
// split bf16 weights, transposed: [out_col][k-pair] (K-major)
__device__ uint32_t g_BT1h[128 * 448], g_BT1l[128 * 448];
__device__ uint32_t g_BT2h[128 * 448], g_BT2l[128 * 448];
__device__ uint32_t g_SW1h[128 * 256], g_SW1l[128 * 256];

// ---------------- helpers ----------------
__device__ __forceinline__ uint32_t smem_u32(const void* p) {
    uint32_t a;
    asm("{ .reg .u64 t; cvta.to.shared.u64 t, %1; cvt.u32.u64 %0, t; }" : "=r"(a) : "l"(p));
    return a;
}
__device__ __forceinline__ void ldm4(uint32_t* r, uint32_t addr) {
    asm volatile("ldmatrix.sync.aligned.m8n8.x4.shared.b16 {%0,%1,%2,%3}, [%4];"
        : "=r"(r[0]), "=r"(r[1]), "=r"(r[2]), "=r"(r[3]) : "r"(addr));
}
__device__ __forceinline__ void mma_bf16(float* d, const uint32_t* a, uint32_t b0, uint32_t b1) {
    asm volatile("mma.sync.aligned.m16n8k16.row.col.f32.bf16.bf16.f32 "
        "{%0,%1,%2,%3}, {%4,%5,%6,%7}, {%8,%9}, {%0,%1,%2,%3};"
        : "+f"(d[0]), "+f"(d[1]), "+f"(d[2]), "+f"(d[3])
        : "r"(a[0]), "r"(a[1]), "r"(a[2]), "r"(a[3]), "r"(b0), "r"(b1));
}
__device__ __forceinline__ uint32_t split_pack_hi(float2 f) {
    __nv_bfloat162 h;
    h.x = __float2bfloat16_rn(f.x); h.y = __float2bfloat16_rn(f.y);
    return *(uint32_t*)&h;
}
__device__ __forceinline__ uint32_t split_pack_lo(float2 f) {
    __nv_bfloat16 hx = __float2bfloat16_rn(f.x), hy = __float2bfloat16_rn(f.y);
    __nv_bfloat162 l;
    l.x = __float2bfloat16_rn(f.x - __bfloat162float(hx));
    l.y = __float2bfloat16_rn(f.y - __bfloat162float(hy));
    return *(uint32_t*)&l;
}
__device__ __forceinline__ void cpa16(uint32_t saddr, const void* g) {
    asm volatile("cp.async.cg.shared.global [%0], [%1], 16;" :: "r"(saddr), "l"(g));
}
#define CP_COMMIT() asm volatile("cp.async.commit_group;" ::: "memory")
#define CP_WAIT(n)  asm volatile("cp.async.wait_group %0;" :: "n"(n) : "memory")

// fused GEMM tile geometry: 128 rows x 64 u32 (K=128 bf16), stride 68 u32 (272 B)
#define FSTR 68
#define FTILE (128 * FSTR * 4)    // 34816
#define FSMEM (4 * FTILE)         // 139264

// ---------------- weight build ----------------
__global__ void k_build_w1(const float* __restrict__ basis, const float* __restrict__ comp,
                           const float* __restrict__ root) {
    int idx = blockIdx.x * blockDim.x + threadIdx.x;
    if (idx >= 128 * 448) return;
    int o = idx / 448, j = idx % 448, k0 = j * 2;
    float w0, w1;
    if (k0 < 768) {
        int r = k0 >> 7, d0 = k0 & 127;
        w0 = 0.f; w1 = 0.f;
        #pragma unroll
        for (int b = 0; b < NB; b++) {
            float cc = comp[r * NB + b];
            w0 += cc * basis[b * 16384 + d0 * 128 + o];
            w1 += cc * basis[b * 16384 + (d0 + 1) * 128 + o];
        }
    } else {
        int d0 = k0 - 768;
        w0 = root[d0 * 128 + o]; w1 = root[(d0 + 1) * 128 + o];
    }
    float2 f = make_float2(w0, w1);
    g_BT1h[idx] = split_pack_hi(f);
    g_BT1l[idx] = split_pack_lo(f);
}
__global__ void k_build_w2(const float* __restrict__ basis, const float* __restrict__ comp,
                           const float* __restrict__ root) {
    int idx = blockIdx.x * blockDim.x + threadIdx.x;
    if (idx >= 128 * 448) return;
    int o = idx / 448, j = idx % 448, k0 = j * 2;
    float w0, w1;
    if (k0 < 768) {
        int r = k0 >> 7, d0 = k0 & 127;
        w0 = 0.f; w1 = 0.f;
        #pragma unroll
        for (int b = 0; b < NB; b++) {
            float cc = comp[r * NB + b];
            w0 += cc * basis[b * 16384 + d0 * 128 + o];
            w1 += cc * basis[b * 16384 + (d0 + 1) * 128 + o];
        }
    } else {
        int d0 = k0 - 768;
        w0 = root[d0 * 128 + o]; w1 = root[(d0 + 1) * 128 + o];
    }
    float2 f = make_float2(w0, w1);
    g_BT2h[idx] = split_pack_hi(f);
    g_BT2l[idx] = split_pack_lo(f);
}
__global__ void k_build_sw1t(const float* __restrict__ sw1) {
    int idx = blockIdx.x * blockDim.x + threadIdx.x;
    if (idx >= 128 * 256) return;
    int o = idx >> 8, j = idx & 255, k0 = j * 2;
    float2 f = make_float2(sw1[k0 * 128 + o], sw1[(k0 + 1) * 128 + o]);
    g_SW1h[idx] = split_pack_hi(f);
    g_SW1l[idx] = split_pack_lo(f);
}

// ---------------- CSR build ----------------
__global__ void k_zero_cnt() {
    int i = blockIdx.x * blockDim.x + threadIdx.x;
    if (i < NSEG1) g_cnt[i] = 0;
}
__global__ void k_count(const int* __restrict__ ei, const int* __restrict__ et) {
    int e = blockIdx.x * blockDim.x + threadIdx.x;
    if (e < NE) atomicAdd(&g_cnt[ei[NE + e] * NREL + et[e]], 1);
}
__global__ __launch_bounds__(SCAN_BLK) void k_scan_a() {
    __shared__ int sm[SCAN_BLK];
    int t = threadIdx.x;
    int gid = blockIdx.x * SCAN_BLK + t;
    int v = (gid < NSEG1) ? g_cnt[gid] : 0;
    sm[t] = v;
    __syncthreads();
    for (int d = 1; d < SCAN_BLK; d <<= 1) {
        int x = (t >= d) ? sm[t - d] : 0;
        __syncthreads();
        sm[t] += x;
        __syncthreads();
    }
    if (gid < NSEG1) g_off[gid] = sm[t] - v;
    if (t == SCAN_BLK - 1) g_bsum[blockIdx.x] = sm[t];
}
__global__ __launch_bounds__(512) void k_scan_b() {
    __shared__ int sm[512];
    int t = threadIdx.x;
    int v = (t < NBLK) ? g_bsum[t] : 0;
    sm[t] = v;
    __syncthreads();
    for (int d = 1; d < 512; d <<= 1) {
        int x = (t >= d) ? sm[t - d] : 0;
        __syncthreads();
        sm[t] += x;
        __syncthreads();
    }
    if (t < NBLK) g_bpre[t] = sm[t] - v;
}
__global__ __launch_bounds__(SCAN_BLK) void k_scan_c() {
    int gid = blockIdx.x * SCAN_BLK + threadIdx.x;
    if (gid < NSEG1) {
        int o = g_off[gid] + g_bpre[blockIdx.x];
        g_off[gid] = o;
        g_cursor[gid] = o;
    }
    if (gid == 0) g_off[NSEG1] = NE;
}
__global__ void k_fill(const int* __restrict__ ei, const int* __restrict__ et) {
    int e = blockIdx.x * blockDim.x + threadIdx.x;
    if (e < NE) {
        int seg = ei[NE + e] * NREL + et[e];
        int pos = atomicAdd(&g_cursor[seg], 1);
        g_esrc[pos] = ei[e];
    }
}

// ---------------- fused-gather GEMM machinery ----------------
// segment mean (warp-collective, lane owns 4 dims)
__device__ __forceinline__ float4 seg_mean(const float* __restrict__ X, int seg, int lane) {
    int s0 = g_off[seg], s1 = g_off[seg + 1];
    float4 a = make_float4(0.f, 0.f, 0.f, 0.f);
    for (int e = s0; e < s1; e++) {
        const float4 v = *(const float4*)(X + (size_t)g_esrc[e] * DIM + lane * 4);
        a.x += v.x; a.y += v.y; a.z += v.z; a.w += v.w;
    }
    float sc = (s1 > s0) ? 1.f / (float)(s1 - s0) : 0.f;
    a.x *= sc; a.y *= sc; a.z *= sc; a.w *= sc;
    return a;
}

// stage B chunk c via cp.async: 2048 x 16B per tile
#define STAGE_B(BTH, BTL, c_)                                                       \
    do {                                                                            \
        int cc = (c_);                                                              \
        for (int i = tid; i < 2048; i += 256) {                                     \
            int row = i >> 4, c16 = i & 15;                                         \
            uint32_t so = (uint32_t)(row * 272 + c16 * 16);                         \
            cpa16(sBh + so, (BTH) + (size_t)row * 448 + cc * 64 + c16 * 4);         \
            cpa16(sBl + so, (BTL) + (size_t)row * 448 + cc * 64 + c16 * 4);         \
        }                                                                           \
        CP_COMMIT();                                                                \
    } while (0)

// stage A chunk c: gather means (c<6) or split root rows (c==6)
#define STAGE_A(X, NLIM, c_)                                                        \
    do {                                                                            \
        int cc = (c_);                                                              \
        if (cc < 6) {                                                               \
            for (int i = 0; i < 16; i++) {                                          \
                int row = wid + i * 8;                                              \
                int grow = m0 + row; if (grow >= (NLIM)) grow = (NLIM) - 1;         \
                float4 a = seg_mean((X), grow * NREL + cc, lane);                   \
                float2 f01 = make_float2(a.x, a.y), f23 = make_float2(a.z, a.w);    \
                Ah[row * FSTR + lane * 2]     = split_pack_hi(f01);                 \
                Ah[row * FSTR + lane * 2 + 1] = split_pack_hi(f23);                 \
                Al[row * FSTR + lane * 2]     = split_pack_lo(f01);                 \
                Al[row * FSTR + lane * 2 + 1] = split_pack_lo(f23);                 \
            }                                                                       \
        } else {                                                                    \
            for (int i = tid; i < 128 * 64; i += 256) {                             \
                int row = i >> 6, k2 = i & 63;                                      \
                int grow = m0 + row; if (grow >= (NLIM)) grow = (NLIM) - 1;         \
                float2 f = *(const float2*)((X) + (size_t)grow * DIM + k2 * 2);     \
                Ah[row * FSTR + k2] = split_pack_hi(f);                             \
                Al[row * FSTR + k2] = split_pack_lo(f);                             \
            }                                                                       \
        }                                                                           \
    } while (0)

#define MMA_CHUNK128()                                                              \
    do {                                                                            \
        _Pragma("unroll")                                                           \
        for (int kk8 = 0; kk8 < 8; kk8++) {                                         \
            uint32_t ah[2][4], al[2][4], bh[4][4], bl[4][4];                        \
            _Pragma("unroll")                                                       \
            for (int mt = 0; mt < 2; mt++) {                                        \
                uint32_t off = (uint32_t)((wm * 32 + mt * 16 + lrow) * 272 + kk8 * 32 + lk * 16); \
                ldm4(ah[mt], sAh + off);                                            \
                ldm4(al[mt], sAl + off);                                            \
            }                                                                       \
            _Pragma("unroll")                                                       \
            for (int nt = 0; nt < 4; nt++) {                                        \
                uint32_t off = (uint32_t)((wn * 64 + nt * 16 + lrow) * 272 + kk8 * 32 + lk * 16); \
                ldm4(bh[nt], sBh + off);                                            \
                ldm4(bl[nt], sBl + off);                                            \
            }                                                                       \
            _Pragma("unroll")                                                       \
            for (int mt = 0; mt < 2; mt++)                                          \
                _Pragma("unroll")                                                   \
                for (int nt = 0; nt < 4; nt++) {                                    \
                    mma_bf16(acc[mt][2 * nt],     ah[mt], bh[nt][0], bh[nt][2]);    \
                    mma_bf16(acc[mt][2 * nt + 1], ah[mt], bh[nt][1], bh[nt][3]);    \
                    mma_bf16(acc[mt][2 * nt],     al[mt], bh[nt][0], bh[nt][2]);    \
                    mma_bf16(acc[mt][2 * nt + 1], al[mt], bh[nt][1], bh[nt][3]);    \
                    mma_bf16(acc[mt][2 * nt],     ah[mt], bl[nt][0], bl[nt][2]);    \
                    mma_bf16(acc[mt][2 * nt + 1], ah[mt], bl[nt][1], bl[nt][3]);    \
                }                                                                   \
        }                                                                           \
    } while (0)

// GEMM1 fused: x1 = relu([seg-means(node_emb) | node_emb] @ B1' + bias1)
__global__ __launch_bounds__(256) void k_gemm1_f(const float* __restrict__ X, const float* __restrict__ bias1) {
    extern __shared__ char sm[];
    uint32_t* Ah = (uint32_t*)sm;
    uint32_t* Al = (uint32_t*)(sm + FTILE);
    const uint32_t sAh = smem_u32(sm), sAl = sAh + FTILE, sBh = sAh + 2 * FTILE, sBl = sAh + 3 * FTILE;
    const int tid = threadIdx.x, lane = tid & 31, wid = tid >> 5;
    const int wm = wid & 3, wn = wid >> 2;
    const int lrow = lane & 15, lk = lane >> 4;
    const int m0 = blockIdx.x * 128;

    float acc[2][8][4];
    #pragma unroll
    for (int i = 0; i < 2; i++)
        #pragma unroll
        for (int j = 0; j < 8; j++)
            #pragma unroll
            for (int c = 0; c < 4; c++) acc[i][j][c] = 0.f;

    for (int c = 0; c < 7; c++) {
        STAGE_B(g_BT1h, g_BT1l, c);
        STAGE_A(X, N_NODES, c);
        CP_WAIT(0);
        __syncthreads();
        MMA_CHUNK128();
        __syncthreads();
    }

    const int g = lane >> 2, tc = lane & 3;
    #pragma unroll
    for (int mt = 0; mt < 2; mt++) {
        #pragma unroll
        for (int nb = 0; nb < 8; nb++) {
            int col = wn * 64 + nb * 8 + tc * 2;
            float b0 = bias1[col], b1 = bias1[col + 1];
            int r0 = m0 + wm * 32 + mt * 16 + g;
            if (r0 < N_NODES)
                *(float2*)(g_x1 + (size_t)r0 * DIM + col) =
                    make_float2(fmaxf(acc[mt][nb][0] + b0, 0.f), fmaxf(acc[mt][nb][1] + b1, 0.f));
            int r1 = r0 + 8;
            if (r1 < N_NODES)
                *(float2*)(g_x1 + (size_t)r1 * DIM + col) =
                    make_float2(fmaxf(acc[mt][nb][2] + b0, 0.f), fmaxf(acc[mt][nb][3] + b1, 0.f));
        }
    }
}

// GEMM2 fused: x2 = [seg-means(x1) | x1] @ B2' + bias2
__global__ __launch_bounds__(256) void k_gemm2_f(const float* __restrict__ bias2) {
    extern __shared__ char sm[];
    uint32_t* Ah = (uint32_t*)sm;
    uint32_t* Al = (uint32_t*)(sm + FTILE);
    const uint32_t sAh = smem_u32(sm), sAl = sAh + FTILE, sBh = sAh + 2 * FTILE, sBl = sAh + 3 * FTILE;
    const int tid = threadIdx.x, lane = tid & 31, wid = tid >> 5;
    const int wm = wid & 3, wn = wid >> 2;
    const int lrow = lane & 15, lk = lane >> 4;
    const int m0 = blockIdx.x * 128;

    float acc[2][8][4];
    #pragma unroll
    for (int i = 0; i < 2; i++)
        #pragma unroll
        for (int j = 0; j < 8; j++)
            #pragma unroll
            for (int c = 0; c < 4; c++) acc[i][j][c] = 0.f;

    for (int c = 0; c < 7; c++) {
        STAGE_B(g_BT2h, g_BT2l, c);
        STAGE_A(g_x1, NOUT2, c);
        CP_WAIT(0);
        __syncthreads();
        MMA_CHUNK128();
        __syncthreads();
    }

    const int g = lane >> 2, tc = lane & 3;
    #pragma unroll
    for (int mt = 0; mt < 2; mt++) {
        #pragma unroll
        for (int nb = 0; nb < 8; nb++) {
            int col = wn * 64 + nb * 8 + tc * 2;
            float b0 = bias2[col], b1 = bias2[col + 1];
            int r0 = m0 + wm * 32 + mt * 16 + g;
            if (r0 < NOUT2)
                *(float2*)(g_x2 + (size_t)r0 * DIM + col) =
                    make_float2(acc[mt][nb][0] + b0, acc[mt][nb][1] + b1);
            int r1 = r0 + 8;
            if (r1 < NOUT2)
                *(float2*)(g_x2 + (size_t)r1 * DIM + col) =
                    make_float2(acc[mt][nb][2] + b0, acc[mt][nb][3] + b1);
        }
    }
}

// ---------------- scorer (HMMA, round-5 proven) ----------------
__global__ __launch_bounds__(256) void k_scorer_mma(const int* __restrict__ h_idx, const int* __restrict__ p_idx,
                                                    const float* __restrict__ sb1, const float* __restrict__ sw2,
                                                    const float* __restrict__ sb2, float* __restrict__ out) {
    extern __shared__ char sm[];
    uint32_t* Ah = (uint32_t*)sm;
    uint32_t* Al = (uint32_t*)(sm + FTILE);
    uint32_t* Bh = (uint32_t*)(sm + 2 * FTILE);
    uint32_t* Bl = (uint32_t*)(sm + 3 * FTILE);
    const uint32_t sAh = smem_u32(Ah), sAl = smem_u32(Al), sBh = smem_u32(Bh), sBl = smem_u32(Bl);
    const int tid = threadIdx.x, lane = tid & 31, wid = tid >> 5;
    const int wm = wid & 3, wn = wid >> 2;
    const int lrow = lane & 15, lk = lane >> 4;
    const int pair0 = blockIdx.x * 128;

    float acc[2][8][4];
    #pragma unroll
    for (int i = 0; i < 2; i++)
        #pragma unroll
        for (int j = 0; j < 8; j++)
            #pragma unroll
            for (int c = 0; c < 4; c++) acc[i][j][c] = 0.f;

    for (int c = 0; c < 4; c++) {
        for (int i = tid; i < 128 * 64; i += 256) {
            int row = i >> 6, k2 = i & 63;
            int pr = pair0 + row; if (pr >= NP) pr = NP - 1;
            float2 h = *(const float2*)(g_x2 + (size_t)h_idx[pr] * DIM + k2 * 2);
            float2 p = *(const float2*)(g_x2 + (size_t)(N_HERB + p_idx[pr]) * DIM + k2 * 2);
            float2 f;
            if (c == 0) f = h;
            else if (c == 1) f = p;
            else if (c == 2) f = make_float2(h.x * p.x, h.y * p.y);
            else f = make_float2(fabsf(h.x - p.x), fabsf(h.y - p.y));
            Ah[row * FSTR + k2] = split_pack_hi(f);
            Al[row * FSTR + k2] = split_pack_lo(f);
            Bh[row * FSTR + k2] = g_SW1h[(size_t)row * 256 + c * 64 + k2];
            Bl[row * FSTR + k2] = g_SW1l[(size_t)row * 256 + c * 64 + k2];
        }
        __syncthreads();
        MMA_CHUNK128();
        __syncthreads();
    }

    __syncthreads();
    float* s_part = (float*)sm;              // [128][2]
    const int g = lane >> 2, tc = lane & 3;
    #pragma unroll
    for (int mt = 0; mt < 2; mt++) {
        float s0 = 0.f, s1 = 0.f;
        #pragma unroll
        for (int nb = 0; nb < 8; nb++) {
            int col = wn * 64 + nb * 8 + tc * 2;
            float w0 = sw2[col], w1 = sw2[col + 1];
            float bb0 = sb1[col], bb1 = sb1[col + 1];
            s0 += fmaxf(acc[mt][nb][0] + bb0, 0.f) * w0 + fmaxf(acc[mt][nb][1] + bb1, 0.f) * w1;
            s1 += fmaxf(acc[mt][nb][2] + bb0, 0.f) * w0 + fmaxf(acc[mt][nb][3] + bb1, 0.f) * w1;
        }
        s0 += __shfl_xor_sync(0xffffffff, s0, 1); s0 += __shfl_xor_sync(0xffffffff, s0, 2);
        s1 += __shfl_xor_sync(0xffffffff, s1, 1); s1 += __shfl_xor_sync(0xffffffff, s1, 2);
        if (tc == 0) {
            int r0 = wm * 32 + mt * 16 + g;
            s_part[r0 * 2 + wn] = s0;
            s_part[(r0 + 8) * 2 + wn] = s1;
        }
    }
    __syncthreads();
    if (tid < 128) {
        int pr = pair0 + tid;
        if (pr < NP) out[pr] = s_part[tid * 2] + s_part[tid * 2 + 1] + sb2[0];
    }
}

// ---------------- launch ----------------
extern "C" void kernel_launch(void* const* d_in, const int* in_sizes, int n_in,
                              void* d_out, int out_size) {
    const int*   edge_index = (const int*)d_in[0];
    const int*   edge_type  = (const int*)d_in[1];
    const int*   h_idx      = (const int*)d_in[2];
    const int*   p_idx      = (const int*)d_in[3];
    const float* node_emb   = (const float*)d_in[4];
    const float* basis1 = (const float*)d_in[5];
    const float* comp1  = (const float*)d_in[6];
    const float* root1  = (const float*)d_in[7];
    const float* bias1  = (const float*)d_in[8];
    const float* basis2 = (const float*)d_in[9];
    const float* comp2  = (const float*)d_in[10];
    const float* root2  = (const float*)d_in[11];
    const float* bias2  = (const float*)d_in[12];
    const float* sw1 = (const float*)d_in[13];
    const float* sb1 = (const float*)d_in[14];
    const float* sw2 = (const float*)d_in[15];
    const float* sb2 = (const float*)d_in[16];
    float* out = (float*)d_out;

    cudaFuncSetAttribute(k_gemm1_f, cudaFuncAttributeMaxDynamicSharedMemorySize, FSMEM);
    cudaFuncSetAttribute(k_gemm2_f, cudaFuncAttributeMaxDynamicSharedMemorySize, FSMEM);
    cudaFuncSetAttribute(k_scorer_mma, cudaFuncAttributeMaxDynamicSharedMemorySize, FSMEM);

    k_build_w1<<<(128 * 448 + 255) / 256, 256>>>(basis1, comp1, root1);
    k_build_w2<<<(128 * 448 + 255) / 256, 256>>>(basis2, comp2, root2);
    k_build_sw1t<<<(128 * 256 + 255) / 256, 256>>>(sw1);

    k_zero_cnt<<<(NSEG1 + 255) / 256, 256>>>();
    k_count<<<(NE + 255) / 256, 256>>>(edge_index, edge_type);
    k_scan_a<<<NBLK, SCAN_BLK>>>();
    k_scan_b<<<1, 512>>>();
    k_scan_c<<<NBLK, SCAN_BLK>>>();
    k_fill<<<(NE + 255) / 256, 256>>>(edge_index, edge_type);

    k_gemm1_f<<<(N_NODES + 127) / 128, 256, FSMEM>>>(node_emb, bias1);
    k_gemm2_f<<<(NOUT2 + 127) / 128, 256, FSMEM>>>(bias2);
    k_scorer_mma<<<(NP + 127) / 128, 256, FSMEM>>>(h_idx, p_idx, sb1, sw2, sb2, out);
}

// round 10
// speedup vs baseline: 1.5181x; 1.5181x over previous
#include <cuda_runtime.h>
#include <cuda_bf16.h>
#include <cstdint>

#define N_NODES 60000
#define N_HERB  5000
#define NOUT2   25000
#define DIM     128
#define NREL    6
#define NB      30
#define NE      600000
#define NP      40000
#define NSEG1   (N_NODES * NREL)   // 360000
#define NSEG2   (NOUT2 * NREL)     // 150000
#define SCAN_BLK 1024
#define NBLK    ((NSEG1 + SCAN_BLK - 1) / SCAN_BLK)   // 352

// ---------------- scratch ----------------
__device__ uint32_t g_A1h[(size_t)NSEG1 * 64], g_A1l[(size_t)NSEG1 * 64];
__device__ uint32_t g_A2h[(size_t)NSEG2 * 64], g_A2l[(size_t)NSEG2 * 64];
__device__ uint32_t g_Eh[(size_t)N_NODES * 64], g_El[(size_t)N_NODES * 64];
__device__ uint32_t g_X1h[(size_t)NOUT2 * 64], g_X1l[(size_t)NOUT2 * 64];
__device__ float g_x1[(size_t)N_NODES * DIM];
__device__ float g_x2[(size_t)NOUT2 * DIM];
__device__ int   g_cnt[NSEG1];
__device__ int   g_off[NSEG1 + 1];
__device__ int   g_cursor[NSEG1];
__device__ int   g_esrc[NE];
__device__ int   g_bsum[NBLK];
__device__ uint32_t g_BT1h[128 * 448], g_BT1l[128 * 448];
__device__ uint32_t g_BT2h[128 * 448], g_BT2l[128 * 448];
__device__ uint32_t g_SW1h[128 * 256], g_SW1l[128 * 256];

// ---------------- helpers ----------------
__device__ __forceinline__ uint32_t smem_u32(const void* p) {
    uint32_t a;
    asm("{ .reg .u64 t; cvta.to.shared.u64 t, %1; cvt.u32.u64 %0, t; }" : "=r"(a) : "l"(p));
    return a;
}
__device__ __forceinline__ void ldm4(uint32_t* r, uint32_t addr) {
    asm volatile("ldmatrix.sync.aligned.m8n8.x4.shared.b16 {%0,%1,%2,%3}, [%4];"
        : "=r"(r[0]), "=r"(r[1]), "=r"(r[2]), "=r"(r[3]) : "r"(addr));
}
__device__ __forceinline__ void mma_bf16(float* d, const uint32_t* a, uint32_t b0, uint32_t b1) {
    asm volatile("mma.sync.aligned.m16n8k16.row.col.f32.bf16.bf16.f32 "
        "{%0,%1,%2,%3}, {%4,%5,%6,%7}, {%8,%9}, {%0,%1,%2,%3};"
        : "+f"(d[0]), "+f"(d[1]), "+f"(d[2]), "+f"(d[3])
        : "r"(a[0]), "r"(a[1]), "r"(a[2]), "r"(a[3]), "r"(b0), "r"(b1));
}
__device__ __forceinline__ uint32_t split_pack_hi(float2 f) {
    __nv_bfloat162 h;
    h.x = __float2bfloat16_rn(f.x); h.y = __float2bfloat16_rn(f.y);
    return *(uint32_t*)&h;
}
__device__ __forceinline__ uint32_t split_pack_lo(float2 f) {
    __nv_bfloat16 hx = __float2bfloat16_rn(f.x), hy = __float2bfloat16_rn(f.y);
    __nv_bfloat162 l;
    l.x = __float2bfloat16_rn(f.x - __bfloat162float(hx));
    l.y = __float2bfloat16_rn(f.y - __bfloat162float(hy));
    return *(uint32_t*)&l;
}
__device__ __forceinline__ void cpa16(uint32_t saddr, const void* g) {
    asm volatile("cp.async.cg.shared.global [%0], [%1], 16;" :: "r"(saddr), "l"(g));
}
#define CP_COMMIT() asm volatile("cp.async.commit_group;" ::: "memory")
#define CP_WAIT(n)  asm volatile("cp.async.wait_group %0;" :: "n"(n) : "memory")

// pipelined GEMM tile: 128 rows x 16 u32 (K=32 bf16), padded stride 20 u32 (80 B)
#define PSTR 20
#define PTILE (128 * PSTR * 4)    // 10240 B
#define PSMEM (8 * PTILE)         // 81920 B -> 2 CTAs/SM
// scorer geometry
#define TSTR 68
#define TILE_BYTES (128 * TSTR * 4)   // 34816

// ---------------- weight / emb build ----------------
__global__ void k_build_w1(const float* __restrict__ basis, const float* __restrict__ comp,
                           const float* __restrict__ root) {
    int idx = blockIdx.x * blockDim.x + threadIdx.x;
    if (idx >= 128 * 448) return;
    int o = idx / 448, j = idx % 448, k0 = j * 2;
    float w0, w1;
    if (k0 < 768) {
        int r = k0 >> 7, d0 = k0 & 127;
        w0 = 0.f; w1 = 0.f;
        #pragma unroll
        for (int b = 0; b < NB; b++) {
            float cc = comp[r * NB + b];
            w0 += cc * basis[b * 16384 + d0 * 128 + o];
            w1 += cc * basis[b * 16384 + (d0 + 1) * 128 + o];
        }
    } else {
        int d0 = k0 - 768;
        w0 = root[d0 * 128 + o]; w1 = root[(d0 + 1) * 128 + o];
    }
    float2 f = make_float2(w0, w1);
    g_BT1h[idx] = split_pack_hi(f);
    g_BT1l[idx] = split_pack_lo(f);
}
__global__ void k_build_w2(const float* __restrict__ basis, const float* __restrict__ comp,
                           const float* __restrict__ root) {
    int idx = blockIdx.x * blockDim.x + threadIdx.x;
    if (idx >= 128 * 448) return;
    int o = idx / 448, j = idx % 448, k0 = j * 2;
    float w0, w1;
    if (k0 < 768) {
        int r = k0 >> 7, d0 = k0 & 127;
        w0 = 0.f; w1 = 0.f;
        #pragma unroll
        for (int b = 0; b < NB; b++) {
            float cc = comp[r * NB + b];
            w0 += cc * basis[b * 16384 + d0 * 128 + o];
            w1 += cc * basis[b * 16384 + (d0 + 1) * 128 + o];
        }
    } else {
        int d0 = k0 - 768;
        w0 = root[d0 * 128 + o]; w1 = root[(d0 + 1) * 128 + o];
    }
    float2 f = make_float2(w0, w1);
    g_BT2h[idx] = split_pack_hi(f);
    g_BT2l[idx] = split_pack_lo(f);
}
__global__ void k_build_sw1t(const float* __restrict__ sw1) {
    int idx = blockIdx.x * blockDim.x + threadIdx.x;
    if (idx >= 128 * 256) return;
    int o = idx >> 8, j = idx & 255, k0 = j * 2;
    float2 f = make_float2(sw1[k0 * 128 + o], sw1[(k0 + 1) * 128 + o]);
    g_SW1h[idx] = split_pack_hi(f);
    g_SW1l[idx] = split_pack_lo(f);
}
__global__ void k_build_emb(const float* __restrict__ X) {
    int idx = blockIdx.x * blockDim.x + threadIdx.x;
    if (idx >= N_NODES * 64) return;
    float2 f = ((const float2*)X)[idx];
    g_Eh[idx] = split_pack_hi(f);
    g_El[idx] = split_pack_lo(f);
}

// ---------------- CSR build ----------------
__global__ void k_zero_cnt() {
    int i = blockIdx.x * blockDim.x + threadIdx.x;
    if (i < NSEG1) g_cnt[i] = 0;
}
__global__ void k_count(const int* __restrict__ ei, const int* __restrict__ et) {
    int e = blockIdx.x * blockDim.x + threadIdx.x;
    if (e < NE) atomicAdd(&g_cnt[ei[NE + e] * NREL + et[e]], 1);
}
__global__ __launch_bounds__(SCAN_BLK) void k_scan_a() {
    __shared__ int sm[SCAN_BLK];
    int t = threadIdx.x;
    int gid = blockIdx.x * SCAN_BLK + t;
    int v = (gid < NSEG1) ? g_cnt[gid] : 0;
    sm[t] = v;
    __syncthreads();
    for (int d = 1; d < SCAN_BLK; d <<= 1) {
        int x = (t >= d) ? sm[t - d] : 0;
        __syncthreads();
        sm[t] += x;
        __syncthreads();
    }
    if (gid < NSEG1) g_off[gid] = sm[t] - v;
    if (t == SCAN_BLK - 1) g_bsum[blockIdx.x] = sm[t];
}
// scan_b fused: each block reduces its prefix of block sums itself
__global__ __launch_bounds__(SCAN_BLK) void k_scan_c() {
    __shared__ int red[SCAN_BLK];
    int t = threadIdx.x;
    red[t] = (t < (int)blockIdx.x && t < NBLK) ? g_bsum[t] : 0;
    __syncthreads();
    for (int d = SCAN_BLK / 2; d > 0; d >>= 1) {
        if (t < d) red[t] += red[t + d];
        __syncthreads();
    }
    int pre = red[0];
    int gid = blockIdx.x * SCAN_BLK + t;
    if (gid < NSEG1) {
        int o = g_off[gid] + pre;
        g_off[gid] = o;
        g_cursor[gid] = o;
    }
    if (gid == 0) g_off[NSEG1] = NE;
}
__global__ void k_fill(const int* __restrict__ ei, const int* __restrict__ et) {
    int e = blockIdx.x * blockDim.x + threadIdx.x;
    if (e < NE) {
        int seg = ei[NE + e] * NREL + et[e];
        int pos = atomicAdd(&g_cursor[seg], 1);
        g_esrc[pos] = ei[e];
    }
}

// ---------------- gathers ----------------
__global__ __launch_bounds__(256) void k_gather1(const float* __restrict__ X) {
    int w = (int)((blockIdx.x * 256u + threadIdx.x) >> 5);
    if (w >= NSEG1) return;
    int lane = threadIdx.x & 31;
    int s0 = g_off[w], s1 = g_off[w + 1];
    float4 acc = make_float4(0.f, 0.f, 0.f, 0.f);
    for (int e = s0; e < s1; e++) {
        const float4 v = *(const float4*)(X + (size_t)g_esrc[e] * DIM + lane * 4);
        acc.x += v.x; acc.y += v.y; acc.z += v.z; acc.w += v.w;
    }
    float sc = (s1 > s0) ? 1.f / (float)(s1 - s0) : 0.f;
    float2 f01 = make_float2(acc.x * sc, acc.y * sc);
    float2 f23 = make_float2(acc.z * sc, acc.w * sc);
    size_t base = (size_t)w * 64 + lane * 2;
    *(uint2*)(g_A1h + base) = make_uint2(split_pack_hi(f01), split_pack_hi(f23));
    *(uint2*)(g_A1l + base) = make_uint2(split_pack_lo(f01), split_pack_lo(f23));
}
__global__ __launch_bounds__(256) void k_gather2() {
    int w = (int)((blockIdx.x * 256u + threadIdx.x) >> 5);
    if (w >= NSEG2) return;
    int lane = threadIdx.x & 31;
    int s0 = g_off[w], s1 = g_off[w + 1];
    float4 acc = make_float4(0.f, 0.f, 0.f, 0.f);
    for (int e = s0; e < s1; e++) {
        const float4 v = *(const float4*)(g_x1 + (size_t)g_esrc[e] * DIM + lane * 4);
        acc.x += v.x; acc.y += v.y; acc.z += v.z; acc.w += v.w;
    }
    float sc = (s1 > s0) ? 1.f / (float)(s1 - s0) : 0.f;
    float2 f01 = make_float2(acc.x * sc, acc.y * sc);
    float2 f23 = make_float2(acc.z * sc, acc.w * sc);
    size_t base = (size_t)w * 64 + lane * 2;
    *(uint2*)(g_A2h + base) = make_uint2(split_pack_hi(f01), split_pack_hi(f23));
    *(uint2*)(g_A2l + base) = make_uint2(split_pack_lo(f01), split_pack_lo(f23));
}

// ---------------- pipelined HMMA GEMM core (K=32 chunks, 28 chunks) ----------------
#define STAGE_CHUNK(c_, s_, AGGH, AGGL, ROOTH, ROOTL, BTH, BTL, NLIM)                         \
    do {                                                                                      \
        int cc = (c_);                                                                        \
        uint32_t sb0 = sbase + (uint32_t)((s_) * 4) * PTILE;                                  \
        _Pragma("unroll")                                                                     \
        for (int k = 0; k < 2; k++) {                                                         \
            int idx = tid + k * 256;                                                          \
            int row = idx >> 2, c16 = idx & 3;                                                \
            int grow = m0 + row; if (grow >= (NLIM)) grow = (NLIM) - 1;                       \
            const uint32_t *srch, *srcl;                                                      \
            if (cc < 24) {                                                                    \
                size_t sgb = ((size_t)grow * 6 + (cc >> 2)) * 64 + (cc & 3) * 16;             \
                srch = (AGGH) + sgb; srcl = (AGGL) + sgb;                                     \
            } else {                                                                          \
                size_t sgb = (size_t)grow * 64 + (cc - 24) * 16;                              \
                srch = (ROOTH) + sgb; srcl = (ROOTL) + sgb;                                   \
            }                                                                                 \
            uint32_t so = (uint32_t)(row * 80 + c16 * 16);                                    \
            cpa16(sb0 + 0 * PTILE + so, srch + c16 * 4);                                      \
            cpa16(sb0 + 1 * PTILE + so, srcl + c16 * 4);                                      \
            const uint32_t* bh = (BTH) + (size_t)row * 448 + cc * 16;                         \
            const uint32_t* bl = (BTL) + (size_t)row * 448 + cc * 16;                         \
            cpa16(sb0 + 2 * PTILE + so, bh + c16 * 4);                                        \
            cpa16(sb0 + 3 * PTILE + so, bl + c16 * 4);                                        \
        }                                                                                     \
        CP_COMMIT();                                                                          \
    } while (0)

#define MMA_CHUNK(s_)                                                                         \
    do {                                                                                      \
        uint32_t sb0 = sbase + (uint32_t)((s_) * 4) * PTILE;                                  \
        _Pragma("unroll")                                                                     \
        for (int kk = 0; kk < 2; kk++) {                                                      \
            uint32_t ah[2][4], al[2][4], bh[4][4], bl[4][4];                                  \
            _Pragma("unroll")                                                                 \
            for (int mt = 0; mt < 2; mt++) {                                                  \
                uint32_t off = (uint32_t)((wm * 32 + mt * 16 + lrow) * 80 + kk * 32 + lk * 16); \
                ldm4(ah[mt], sb0 + 0 * PTILE + off);                                          \
                ldm4(al[mt], sb0 + 1 * PTILE + off);                                          \
            }                                                                                 \
            _Pragma("unroll")                                                                 \
            for (int nt = 0; nt < 4; nt++) {                                                  \
                uint32_t off = (uint32_t)((wn * 64 + nt * 16 + lrow) * 80 + kk * 32 + lk * 16); \
                ldm4(bh[nt], sb0 + 2 * PTILE + off);                                          \
                ldm4(bl[nt], sb0 + 3 * PTILE + off);                                          \
            }                                                                                 \
            _Pragma("unroll")                                                                 \
            for (int mt = 0; mt < 2; mt++)                                                    \
                _Pragma("unroll")                                                             \
                for (int nt = 0; nt < 4; nt++) {                                              \
                    mma_bf16(acc[mt][2 * nt],     ah[mt], bh[nt][0], bh[nt][2]);              \
                    mma_bf16(acc[mt][2 * nt + 1], ah[mt], bh[nt][1], bh[nt][3]);              \
                    mma_bf16(acc[mt][2 * nt],     al[mt], bh[nt][0], bh[nt][2]);              \
                    mma_bf16(acc[mt][2 * nt + 1], al[mt], bh[nt][1], bh[nt][3]);              \
                    mma_bf16(acc[mt][2 * nt],     ah[mt], bl[nt][0], bl[nt][2]);              \
                    mma_bf16(acc[mt][2 * nt + 1], ah[mt], bl[nt][1], bl[nt][3]);              \
                }                                                                             \
        }                                                                                     \
    } while (0)

// GEMM1: x1 = relu([agg1 | emb] @ B1' + bias1); split copy only for rows < NOUT2
__global__ __launch_bounds__(256, 2) void k_gemm1_p(const float* __restrict__ bias1) {
    extern __shared__ char sm[];
    const uint32_t sbase = smem_u32(sm);
    const int tid = threadIdx.x, lane = tid & 31, wid = tid >> 5;
    const int wm = wid & 3, wn = wid >> 2;
    const int lrow = lane & 15, lk = lane >> 4;
    const int m0 = blockIdx.x * 128;

    float acc[2][8][4];
    #pragma unroll
    for (int i = 0; i < 2; i++)
        #pragma unroll
        for (int j = 0; j < 8; j++)
            #pragma unroll
            for (int c = 0; c < 4; c++) acc[i][j][c] = 0.f;

    STAGE_CHUNK(0, 0, g_A1h, g_A1l, g_Eh, g_El, g_BT1h, g_BT1l, N_NODES);
    for (int c = 0; c < 28; c++) {
        int s = c & 1;
        if (c < 27) {
            STAGE_CHUNK(c + 1, s ^ 1, g_A1h, g_A1l, g_Eh, g_El, g_BT1h, g_BT1l, N_NODES);
            CP_WAIT(1);
        } else {
            CP_WAIT(0);
        }
        __syncthreads();
        MMA_CHUNK(s);
        __syncthreads();
    }

    const int g = lane >> 2, tc = lane & 3;
    #pragma unroll
    for (int mt = 0; mt < 2; mt++) {
        #pragma unroll
        for (int nb = 0; nb < 8; nb++) {
            int col = wn * 64 + nb * 8 + tc * 2;
            float b0 = bias1[col], b1 = bias1[col + 1];
            int pi = col >> 1;
            int r0 = m0 + wm * 32 + mt * 16 + g;
            if (r0 < N_NODES) {
                float2 v = make_float2(fmaxf(acc[mt][nb][0] + b0, 0.f), fmaxf(acc[mt][nb][1] + b1, 0.f));
                *(float2*)(g_x1 + (size_t)r0 * DIM + col) = v;
                if (r0 < NOUT2) {
                    g_X1h[(size_t)r0 * 64 + pi] = split_pack_hi(v);
                    g_X1l[(size_t)r0 * 64 + pi] = split_pack_lo(v);
                }
            }
            int r1 = r0 + 8;
            if (r1 < N_NODES) {
                float2 v = make_float2(fmaxf(acc[mt][nb][2] + b0, 0.f), fmaxf(acc[mt][nb][3] + b1, 0.f));
                *(float2*)(g_x1 + (size_t)r1 * DIM + col) = v;
                if (r1 < NOUT2) {
                    g_X1h[(size_t)r1 * 64 + pi] = split_pack_hi(v);
                    g_X1l[(size_t)r1 * 64 + pi] = split_pack_lo(v);
                }
            }
        }
    }
}

// GEMM2: x2 = [agg2 | x1] @ B2' + bias2
__global__ __launch_bounds__(256, 2) void k_gemm2_p(const float* __restrict__ bias2) {
    extern __shared__ char sm[];
    const uint32_t sbase = smem_u32(sm);
    const int tid = threadIdx.x, lane = tid & 31, wid = tid >> 5;
    const int wm = wid & 3, wn = wid >> 2;
    const int lrow = lane & 15, lk = lane >> 4;
    const int m0 = blockIdx.x * 128;

    float acc[2][8][4];
    #pragma unroll
    for (int i = 0; i < 2; i++)
        #pragma unroll
        for (int j = 0; j < 8; j++)
            #pragma unroll
            for (int c = 0; c < 4; c++) acc[i][j][c] = 0.f;

    STAGE_CHUNK(0, 0, g_A2h, g_A2l, g_X1h, g_X1l, g_BT2h, g_BT2l, NOUT2);
    for (int c = 0; c < 28; c++) {
        int s = c & 1;
        if (c < 27) {
            STAGE_CHUNK(c + 1, s ^ 1, g_A2h, g_A2l, g_X1h, g_X1l, g_BT2h, g_BT2l, NOUT2);
            CP_WAIT(1);
        } else {
            CP_WAIT(0);
        }
        __syncthreads();
        MMA_CHUNK(s);
        __syncthreads();
    }

    const int g = lane >> 2, tc = lane & 3;
    #pragma unroll
    for (int mt = 0; mt < 2; mt++) {
        #pragma unroll
        for (int nb = 0; nb < 8; nb++) {
            int col = wn * 64 + nb * 8 + tc * 2;
            float b0 = bias2[col], b1 = bias2[col + 1];
            int r0 = m0 + wm * 32 + mt * 16 + g;
            if (r0 < NOUT2)
                *(float2*)(g_x2 + (size_t)r0 * DIM + col) =
                    make_float2(acc[mt][nb][0] + b0, acc[mt][nb][1] + b1);
            int r1 = r0 + 8;
            if (r1 < NOUT2)
                *(float2*)(g_x2 + (size_t)r1 * DIM + col) =
                    make_float2(acc[mt][nb][2] + b0, acc[mt][nb][3] + b1);
        }
    }
}

// ---------------- scorer (HMMA) — minimal per-chunk loads + cp.async B ----------------
__global__ __launch_bounds__(256) void k_scorer_mma(const int* __restrict__ h_idx, const int* __restrict__ p_idx,
                                                    const float* __restrict__ sb1, const float* __restrict__ sw2,
                                                    const float* __restrict__ sb2, float* __restrict__ out) {
    extern __shared__ char sm[];
    __shared__ int sh_h[128], sh_p[128];
    uint32_t* Ah = (uint32_t*)sm;
    uint32_t* Al = (uint32_t*)(sm + TILE_BYTES);
    const uint32_t sAh = smem_u32(sm), sAl = sAh + TILE_BYTES, sBh = sAh + 2 * TILE_BYTES, sBl = sAh + 3 * TILE_BYTES;
    const int tid = threadIdx.x, lane = tid & 31, wid = tid >> 5;
    const int wm = wid & 3, wn = wid >> 2;
    const int lrow = lane & 15, lk = lane >> 4;
    const int pair0 = blockIdx.x * 128;

    for (int i = tid; i < 128; i += 256) {
        int pr = pair0 + i; if (pr >= NP) pr = NP - 1;
        sh_h[i] = h_idx[pr];
        sh_p[i] = N_HERB + p_idx[pr];
    }
    __syncthreads();

    float acc[2][8][4];
    #pragma unroll
    for (int i = 0; i < 2; i++)
        #pragma unroll
        for (int j = 0; j < 8; j++)
            #pragma unroll
            for (int c = 0; c < 4; c++) acc[i][j][c] = 0.f;

    for (int c = 0; c < 4; c++) {
        // stage B via cp.async: 128 rows x 16 x 16B = 2048 transfers
        for (int i = tid; i < 2048; i += 256) {
            int row = i >> 4, c16 = i & 15;
            uint32_t so = (uint32_t)(row * 272 + c16 * 16);
            cpa16(sBh + so, g_SW1h + (size_t)row * 256 + c * 64 + c16 * 4);
            cpa16(sBl + so, g_SW1l + (size_t)row * 256 + c * 64 + c16 * 4);
        }
        CP_COMMIT();
        // stage A: only the loads this chunk needs
        for (int i = tid; i < 128 * 64; i += 256) {
            int row = i >> 6, k2 = i & 63;
            float2 f;
            if (c == 0)      f = *(const float2*)(g_x2 + (size_t)sh_h[row] * DIM + k2 * 2);
            else if (c == 1) f = *(const float2*)(g_x2 + (size_t)sh_p[row] * DIM + k2 * 2);
            else {
                float2 h = *(const float2*)(g_x2 + (size_t)sh_h[row] * DIM + k2 * 2);
                float2 p = *(const float2*)(g_x2 + (size_t)sh_p[row] * DIM + k2 * 2);
                if (c == 2) f = make_float2(h.x * p.x, h.y * p.y);
                else        f = make_float2(fabsf(h.x - p.x), fabsf(h.y - p.y));
            }
            Ah[row * TSTR + k2] = split_pack_hi(f);
            Al[row * TSTR + k2] = split_pack_lo(f);
        }
        CP_WAIT(0);
        __syncthreads();
        #pragma unroll
        for (int kk8 = 0; kk8 < 8; kk8++) {
            uint32_t ah[2][4], al[2][4], bh[4][4], bl[4][4];
            #pragma unroll
            for (int mt = 0; mt < 2; mt++) {
                uint32_t off = (uint32_t)((wm * 32 + mt * 16 + lrow) * 272 + kk8 * 32 + lk * 16);
                ldm4(ah[mt], sAh + off);
                ldm4(al[mt], sAl + off);
            }
            #pragma unroll
            for (int nt = 0; nt < 4; nt++) {
                uint32_t off = (uint32_t)((wn * 64 + nt * 16 + lrow) * 272 + kk8 * 32 + lk * 16);
                ldm4(bh[nt], sBh + off);
                ldm4(bl[nt], sBl + off);
            }
            #pragma unroll
            for (int mt = 0; mt < 2; mt++)
                #pragma unroll
                for (int nt = 0; nt < 4; nt++) {
                    mma_bf16(acc[mt][2 * nt],     ah[mt], bh[nt][0], bh[nt][2]);
                    mma_bf16(acc[mt][2 * nt + 1], ah[mt], bh[nt][1], bh[nt][3]);
                    mma_bf16(acc[mt][2 * nt],     al[mt], bh[nt][0], bh[nt][2]);
                    mma_bf16(acc[mt][2 * nt + 1], al[mt], bh[nt][1], bh[nt][3]);
                    mma_bf16(acc[mt][2 * nt],     ah[mt], bl[nt][0], bl[nt][2]);
                    mma_bf16(acc[mt][2 * nt + 1], ah[mt], bl[nt][1], bl[nt][3]);
                }
        }
        __syncthreads();
    }

    __syncthreads();
    float* s_part = (float*)sm;              // [128][2]
    const int g = lane >> 2, tc = lane & 3;
    #pragma unroll
    for (int mt = 0; mt < 2; mt++) {
        float s0 = 0.f, s1 = 0.f;
        #pragma unroll
        for (int nb = 0; nb < 8; nb++) {
            int col = wn * 64 + nb * 8 + tc * 2;
            float w0 = sw2[col], w1 = sw2[col + 1];
            float bb0 = sb1[col], bb1 = sb1[col + 1];
            s0 += fmaxf(acc[mt][nb][0] + bb0, 0.f) * w0 + fmaxf(acc[mt][nb][1] + bb1, 0.f) * w1;
            s1 += fmaxf(acc[mt][nb][2] + bb0, 0.f) * w0 + fmaxf(acc[mt][nb][3] + bb1, 0.f) * w1;
        }
        s0 += __shfl_xor_sync(0xffffffff, s0, 1); s0 += __shfl_xor_sync(0xffffffff, s0, 2);
        s1 += __shfl_xor_sync(0xffffffff, s1, 1); s1 += __shfl_xor_sync(0xffffffff, s1, 2);
        if (tc == 0) {
            int r0 = wm * 32 + mt * 16 + g;
            s_part[r0 * 2 + wn] = s0;
            s_part[(r0 + 8) * 2 + wn] = s1;
        }
    }
    __syncthreads();
    if (tid < 128) {
        int pr = pair0 + tid;
        if (pr < NP) out[pr] = s_part[tid * 2] + s_part[tid * 2 + 1] + sb2[0];
    }
}

// ---------------- launch ----------------
extern "C" void kernel_launch(void* const* d_in, const int* in_sizes, int n_in,
                              void* d_out, int out_size) {
    const int*   edge_index = (const int*)d_in[0];
    const int*   edge_type  = (const int*)d_in[1];
    const int*   h_idx      = (const int*)d_in[2];
    const int*   p_idx      = (const int*)d_in[3];
    const float* node_emb   = (const float*)d_in[4];
    const float* basis1 = (const float*)d_in[5];
    const float* comp1  = (const float*)d_in[6];
    const float* root1  = (const float*)d_in[7];
    const float* bias1  = (const float*)d_in[8];
    const float* basis2 = (const float*)d_in[9];
    const float* comp2  = (const float*)d_in[10];
    const float* root2  = (const float*)d_in[11];
    const float* bias2  = (const float*)d_in[12];
    const float* sw1 = (const float*)d_in[13];
    const float* sb1 = (const float*)d_in[14];
    const float* sw2 = (const float*)d_in[15];
    const float* sb2 = (const float*)d_in[16];
    float* out = (float*)d_out;

    cudaFuncSetAttribute(k_gemm1_p, cudaFuncAttributeMaxDynamicSharedMemorySize, PSMEM);
    cudaFuncSetAttribute(k_gemm2_p, cudaFuncAttributeMaxDynamicSharedMemorySize, PSMEM);
    cudaFuncSetAttribute(k_scorer_mma, cudaFuncAttributeMaxDynamicSharedMemorySize, 4 * TILE_BYTES);

    k_build_w1<<<(128 * 448 + 255) / 256, 256>>>(basis1, comp1, root1);
    k_build_w2<<<(128 * 448 + 255) / 256, 256>>>(basis2, comp2, root2);
    k_build_sw1t<<<(128 * 256 + 255) / 256, 256>>>(sw1);
    k_build_emb<<<(N_NODES * 64 + 255) / 256, 256>>>(node_emb);

    k_zero_cnt<<<(NSEG1 + 255) / 256, 256>>>();
    k_count<<<(NE + 255) / 256, 256>>>(edge_index, edge_type);
    k_scan_a<<<NBLK, SCAN_BLK>>>();
    k_scan_c<<<NBLK, SCAN_BLK>>>();
    k_fill<<<(NE + 255) / 256, 256>>>(edge_index, edge_type);

    k_gather1<<<(NSEG1 * 32 + 255) / 256, 256>>>(node_emb);
    k_gemm1_p<<<(N_NODES + 127) / 128, 256, PSMEM>>>(bias1);

    k_gather2<<<(NSEG2 * 32 + 255) / 256, 256>>>();
    k_gemm2_p<<<(NOUT2 + 127) / 128, 256, PSMEM>>>(bias2);

    k_scorer_mma<<<(NP + 127) / 128, 256, 4 * TILE_BYTES>>>(h_idx, p_idx, sb1, sw2, sb2, out);
}

// round 11
// speedup vs baseline: 1.5704x; 1.0345x over previous
#include <cuda_runtime.h>
#include <cuda_bf16.h>
#include <cstdint>

#define N_NODES 60000
#define N_HERB  5000
#define NOUT2   25000
#define DIM     128
#define NREL    6
#define NB      30
#define NE      600000
#define NP      40000
#define NSEG1   (N_NODES * NREL)   // 360000
#define NSEG2   (NOUT2 * NREL)     // 150000
#define SCAN_BLK 1024
#define NBLK    ((NSEG1 + SCAN_BLK - 1) / SCAN_BLK)   // 352

// ---------------- scratch ----------------
__device__ uint32_t g_A1h[(size_t)NSEG1 * 64], g_A1l[(size_t)NSEG1 * 64];
__device__ uint32_t g_A2h[(size_t)NSEG2 * 64], g_A2l[(size_t)NSEG2 * 64];
__device__ uint32_t g_Eh[(size_t)N_NODES * 64], g_El[(size_t)N_NODES * 64];
__device__ uint32_t g_X1h[(size_t)NOUT2 * 64], g_X1l[(size_t)NOUT2 * 64];
__device__ float g_x1[(size_t)N_NODES * DIM];
__device__ float g_x2[(size_t)NOUT2 * DIM];
__device__ int   g_cnt[NSEG1];
__device__ int   g_off[NSEG1 + 1];
__device__ int   g_cursor[NSEG1];
__device__ int   g_esrc[NE];
__device__ int   g_bsum[NBLK];
__device__ uint32_t g_BT1h[128 * 448], g_BT1l[128 * 448];
__device__ uint32_t g_BT2h[128 * 448], g_BT2l[128 * 448];
__device__ uint32_t g_SW1h[128 * 256], g_SW1l[128 * 256];

// ---------------- helpers ----------------
__device__ __forceinline__ uint32_t smem_u32(const void* p) {
    uint32_t a;
    asm("{ .reg .u64 t; cvta.to.shared.u64 t, %1; cvt.u32.u64 %0, t; }" : "=r"(a) : "l"(p));
    return a;
}
__device__ __forceinline__ void ldm4(uint32_t* r, uint32_t addr) {
    asm volatile("ldmatrix.sync.aligned.m8n8.x4.shared.b16 {%0,%1,%2,%3}, [%4];"
        : "=r"(r[0]), "=r"(r[1]), "=r"(r[2]), "=r"(r[3]) : "r"(addr));
}
__device__ __forceinline__ void mma_bf16(float* d, const uint32_t* a, uint32_t b0, uint32_t b1) {
    asm volatile("mma.sync.aligned.m16n8k16.row.col.f32.bf16.bf16.f32 "
        "{%0,%1,%2,%3}, {%4,%5,%6,%7}, {%8,%9}, {%0,%1,%2,%3};"
        : "+f"(d[0]), "+f"(d[1]), "+f"(d[2]), "+f"(d[3])
        : "r"(a[0]), "r"(a[1]), "r"(a[2]), "r"(a[3]), "r"(b0), "r"(b1));
}
__device__ __forceinline__ uint32_t split_pack_hi(float2 f) {
    __nv_bfloat162 h;
    h.x = __float2bfloat16_rn(f.x); h.y = __float2bfloat16_rn(f.y);
    return *(uint32_t*)&h;
}
__device__ __forceinline__ uint32_t split_pack_lo(float2 f) {
    __nv_bfloat16 hx = __float2bfloat16_rn(f.x), hy = __float2bfloat16_rn(f.y);
    __nv_bfloat162 l;
    l.x = __float2bfloat16_rn(f.x - __bfloat162float(hx));
    l.y = __float2bfloat16_rn(f.y - __bfloat162float(hy));
    return *(uint32_t*)&l;
}
__device__ __forceinline__ void cpa16(uint32_t saddr, const void* g) {
    asm volatile("cp.async.cg.shared.global [%0], [%1], 16;" :: "r"(saddr), "l"(g));
}
#define CP_COMMIT() asm volatile("cp.async.commit_group;" ::: "memory")
#define CP_WAIT(n)  asm volatile("cp.async.wait_group %0;" :: "n"(n) : "memory")

// pipelined GEMM tile: 128 rows x 16 u32 (K=32 bf16), padded stride 20 u32 (80 B)
#define PSTR 20
#define PTILE (128 * PSTR * 4)    // 10240 B
#define PSMEM (8 * PTILE)         // 81920 B -> 2 CTAs/SM
// scorer geometry
#define TSTR 68
#define TILE_BYTES (128 * TSTR * 4)   // 34816

// ---------------- merged weight/emb build (one kernel, range-dispatched) ----------------
// ranges: [0, 57344)           -> BT1
//         [57344, 114688)      -> BT2
//         [114688, 147456)     -> SW1
//         [147456, 147456+3.84M) -> emb split
#define BLD_W1   (128 * 448)                 // 57344
#define BLD_W2   (BLD_W1 + 128 * 448)        // 114688
#define BLD_SW   (BLD_W2 + 128 * 256)        // 147456
#define BLD_EMB  (BLD_SW + N_NODES * 64)     // 3987456
__global__ void k_build_all(const float* __restrict__ basis1, const float* __restrict__ comp1,
                            const float* __restrict__ root1,
                            const float* __restrict__ basis2, const float* __restrict__ comp2,
                            const float* __restrict__ root2,
                            const float* __restrict__ sw1, const float* __restrict__ X) {
    int gid = blockIdx.x * blockDim.x + threadIdx.x;
    if (gid >= BLD_EMB) return;
    if (gid < BLD_W2) {
        // weight build, layer sel
        const float* basis = (gid < BLD_W1) ? basis1 : basis2;
        const float* comp  = (gid < BLD_W1) ? comp1 : comp2;
        const float* root  = (gid < BLD_W1) ? root1 : root2;
        uint32_t* dh = (gid < BLD_W1) ? g_BT1h : g_BT2h;
        uint32_t* dl = (gid < BLD_W1) ? g_BT1l : g_BT2l;
        int idx = (gid < BLD_W1) ? gid : gid - BLD_W1;
        int o = idx / 448, j = idx % 448, k0 = j * 2;
        float w0, w1;
        if (k0 < 768) {
            int r = k0 >> 7, d0 = k0 & 127;
            w0 = 0.f; w1 = 0.f;
            #pragma unroll
            for (int b = 0; b < NB; b++) {
                float cc = comp[r * NB + b];
                w0 += cc * basis[b * 16384 + d0 * 128 + o];
                w1 += cc * basis[b * 16384 + (d0 + 1) * 128 + o];
            }
        } else {
            int d0 = k0 - 768;
            w0 = root[d0 * 128 + o]; w1 = root[(d0 + 1) * 128 + o];
        }
        float2 f = make_float2(w0, w1);
        dh[idx] = split_pack_hi(f);
        dl[idx] = split_pack_lo(f);
    } else if (gid < BLD_SW) {
        int idx = gid - BLD_W2;
        int o = idx >> 8, j = idx & 255, k0 = j * 2;
        float2 f = make_float2(sw1[k0 * 128 + o], sw1[(k0 + 1) * 128 + o]);
        g_SW1h[idx] = split_pack_hi(f);
        g_SW1l[idx] = split_pack_lo(f);
    } else {
        int idx = gid - BLD_SW;
        float2 f = ((const float2*)X)[idx];
        g_Eh[idx] = split_pack_hi(f);
        g_El[idx] = split_pack_lo(f);
    }
}

// ---------------- CSR build ----------------
__global__ void k_count(const int* __restrict__ ei, const int* __restrict__ et) {
    int e = blockIdx.x * blockDim.x + threadIdx.x;
    if (e < NE) atomicAdd(&g_cnt[ei[NE + e] * NREL + et[e]], 1);
}
__global__ __launch_bounds__(SCAN_BLK) void k_scan_a() {
    __shared__ int sm[SCAN_BLK];
    int t = threadIdx.x;
    int gid = blockIdx.x * SCAN_BLK + t;
    int v = (gid < NSEG1) ? g_cnt[gid] : 0;
    sm[t] = v;
    __syncthreads();
    for (int d = 1; d < SCAN_BLK; d <<= 1) {
        int x = (t >= d) ? sm[t - d] : 0;
        __syncthreads();
        sm[t] += x;
        __syncthreads();
    }
    if (gid < NSEG1) g_off[gid] = sm[t] - v;
    if (t == SCAN_BLK - 1) g_bsum[blockIdx.x] = sm[t];
}
__global__ __launch_bounds__(SCAN_BLK) void k_scan_c() {
    __shared__ int red[SCAN_BLK];
    int t = threadIdx.x;
    red[t] = (t < (int)blockIdx.x && t < NBLK) ? g_bsum[t] : 0;
    __syncthreads();
    for (int d = SCAN_BLK / 2; d > 0; d >>= 1) {
        if (t < d) red[t] += red[t + d];
        __syncthreads();
    }
    int pre = red[0];
    int gid = blockIdx.x * SCAN_BLK + t;
    if (gid < NSEG1) {
        int o = g_off[gid] + pre;
        g_off[gid] = o;
        g_cursor[gid] = o;
    }
    if (gid == 0) g_off[NSEG1] = NE;
}
__global__ void k_fill(const int* __restrict__ ei, const int* __restrict__ et) {
    int e = blockIdx.x * blockDim.x + threadIdx.x;
    if (e < NE) {
        int seg = ei[NE + e] * NREL + et[e];
        int pos = atomicAdd(&g_cursor[seg], 1);
        g_esrc[pos] = ei[e];
    }
}

// ---------------- gathers ----------------
__global__ __launch_bounds__(256) void k_gather1(const float* __restrict__ X) {
    int w = (int)((blockIdx.x * 256u + threadIdx.x) >> 5);
    if (w >= NSEG1) return;
    int lane = threadIdx.x & 31;
    int s0 = g_off[w], s1 = g_off[w + 1];
    float4 acc = make_float4(0.f, 0.f, 0.f, 0.f);
    for (int e = s0; e < s1; e++) {
        const float4 v = *(const float4*)(X + (size_t)g_esrc[e] * DIM + lane * 4);
        acc.x += v.x; acc.y += v.y; acc.z += v.z; acc.w += v.w;
    }
    float sc = (s1 > s0) ? 1.f / (float)(s1 - s0) : 0.f;
    float2 f01 = make_float2(acc.x * sc, acc.y * sc);
    float2 f23 = make_float2(acc.z * sc, acc.w * sc);
    size_t base = (size_t)w * 64 + lane * 2;
    *(uint2*)(g_A1h + base) = make_uint2(split_pack_hi(f01), split_pack_hi(f23));
    *(uint2*)(g_A1l + base) = make_uint2(split_pack_lo(f01), split_pack_lo(f23));
}
__global__ __launch_bounds__(256) void k_gather2() {
    int w = (int)((blockIdx.x * 256u + threadIdx.x) >> 5);
    if (w >= NSEG2) return;
    int lane = threadIdx.x & 31;
    int s0 = g_off[w], s1 = g_off[w + 1];
    float4 acc = make_float4(0.f, 0.f, 0.f, 0.f);
    for (int e = s0; e < s1; e++) {
        const float4 v = *(const float4*)(g_x1 + (size_t)g_esrc[e] * DIM + lane * 4);
        acc.x += v.x; acc.y += v.y; acc.z += v.z; acc.w += v.w;
    }
    float sc = (s1 > s0) ? 1.f / (float)(s1 - s0) : 0.f;
    float2 f01 = make_float2(acc.x * sc, acc.y * sc);
    float2 f23 = make_float2(acc.z * sc, acc.w * sc);
    size_t base = (size_t)w * 64 + lane * 2;
    *(uint2*)(g_A2h + base) = make_uint2(split_pack_hi(f01), split_pack_hi(f23));
    *(uint2*)(g_A2l + base) = make_uint2(split_pack_lo(f01), split_pack_lo(f23));
}

// ---------------- pipelined HMMA GEMM core (K=32 chunks, 28 chunks) ----------------
#define STAGE_CHUNK(c_, s_, AGGH, AGGL, ROOTH, ROOTL, BTH, BTL, NLIM)                         \
    do {                                                                                      \
        int cc = (c_);                                                                        \
        uint32_t sb0 = sbase + (uint32_t)((s_) * 4) * PTILE;                                  \
        _Pragma("unroll")                                                                     \
        for (int k = 0; k < 2; k++) {                                                         \
            int idx = tid + k * 256;                                                          \
            int row = idx >> 2, c16 = idx & 3;                                                \
            int grow = m0 + row; if (grow >= (NLIM)) grow = (NLIM) - 1;                       \
            const uint32_t *srch, *srcl;                                                      \
            if (cc < 24) {                                                                    \
                size_t sgb = ((size_t)grow * 6 + (cc >> 2)) * 64 + (cc & 3) * 16;             \
                srch = (AGGH) + sgb; srcl = (AGGL) + sgb;                                     \
            } else {                                                                          \
                size_t sgb = (size_t)grow * 64 + (cc - 24) * 16;                              \
                srch = (ROOTH) + sgb; srcl = (ROOTL) + sgb;                                   \
            }                                                                                 \
            uint32_t so = (uint32_t)(row * 80 + c16 * 16);                                    \
            cpa16(sb0 + 0 * PTILE + so, srch + c16 * 4);                                      \
            cpa16(sb0 + 1 * PTILE + so, srcl + c16 * 4);                                      \
            const uint32_t* bh = (BTH) + (size_t)row * 448 + cc * 16;                         \
            const uint32_t* bl = (BTL) + (size_t)row * 448 + cc * 16;                         \
            cpa16(sb0 + 2 * PTILE + so, bh + c16 * 4);                                        \
            cpa16(sb0 + 3 * PTILE + so, bl + c16 * 4);                                        \
        }                                                                                     \
        CP_COMMIT();                                                                          \
    } while (0)

#define MMA_CHUNK(s_)                                                                         \
    do {                                                                                      \
        uint32_t sb0 = sbase + (uint32_t)((s_) * 4) * PTILE;                                  \
        _Pragma("unroll")                                                                     \
        for (int kk = 0; kk < 2; kk++) {                                                      \
            uint32_t ah[2][4], al[2][4], bh[4][4], bl[4][4];                                  \
            _Pragma("unroll")                                                                 \
            for (int mt = 0; mt < 2; mt++) {                                                  \
                uint32_t off = (uint32_t)((wm * 32 + mt * 16 + lrow) * 80 + kk * 32 + lk * 16); \
                ldm4(ah[mt], sb0 + 0 * PTILE + off);                                          \
                ldm4(al[mt], sb0 + 1 * PTILE + off);                                          \
            }                                                                                 \
            _Pragma("unroll")                                                                 \
            for (int nt = 0; nt < 4; nt++) {                                                  \
                uint32_t off = (uint32_t)((wn * 64 + nt * 16 + lrow) * 80 + kk * 32 + lk * 16); \
                ldm4(bh[nt], sb0 + 2 * PTILE + off);                                          \
                ldm4(bl[nt], sb0 + 3 * PTILE + off);                                          \
            }                                                                                 \
            _Pragma("unroll")                                                                 \
            for (int mt = 0; mt < 2; mt++)                                                    \
                _Pragma("unroll")                                                             \
                for (int nt = 0; nt < 4; nt++) {                                              \
                    mma_bf16(acc[mt][2 * nt],     ah[mt], bh[nt][0], bh[nt][2]);              \
                    mma_bf16(acc[mt][2 * nt + 1], ah[mt], bh[nt][1], bh[nt][3]);              \
                    mma_bf16(acc[mt][2 * nt],     al[mt], bh[nt][0], bh[nt][2]);              \
                    mma_bf16(acc[mt][2 * nt + 1], al[mt], bh[nt][1], bh[nt][3]);              \
                    mma_bf16(acc[mt][2 * nt],     ah[mt], bl[nt][0], bl[nt][2]);              \
                    mma_bf16(acc[mt][2 * nt + 1], ah[mt], bl[nt][1], bl[nt][3]);              \
                }                                                                             \
        }                                                                                     \
    } while (0)

// GEMM1: x1 = relu([agg1 | emb] @ B1' + bias1); split copy only for rows < NOUT2
__global__ __launch_bounds__(256, 2) void k_gemm1_p(const float* __restrict__ bias1) {
    extern __shared__ char sm[];
    const uint32_t sbase = smem_u32(sm);
    const int tid = threadIdx.x, lane = tid & 31, wid = tid >> 5;
    const int wm = wid & 3, wn = wid >> 2;
    const int lrow = lane & 15, lk = lane >> 4;
    const int m0 = blockIdx.x * 128;

    float acc[2][8][4];
    #pragma unroll
    for (int i = 0; i < 2; i++)
        #pragma unroll
        for (int j = 0; j < 8; j++)
            #pragma unroll
            for (int c = 0; c < 4; c++) acc[i][j][c] = 0.f;

    STAGE_CHUNK(0, 0, g_A1h, g_A1l, g_Eh, g_El, g_BT1h, g_BT1l, N_NODES);
    for (int c = 0; c < 28; c++) {
        int s = c & 1;
        if (c < 27) {
            STAGE_CHUNK(c + 1, s ^ 1, g_A1h, g_A1l, g_Eh, g_El, g_BT1h, g_BT1l, N_NODES);
            CP_WAIT(1);
        } else {
            CP_WAIT(0);
        }
        __syncthreads();
        MMA_CHUNK(s);
        __syncthreads();
    }

    const int g = lane >> 2, tc = lane & 3;
    #pragma unroll
    for (int mt = 0; mt < 2; mt++) {
        #pragma unroll
        for (int nb = 0; nb < 8; nb++) {
            int col = wn * 64 + nb * 8 + tc * 2;
            float b0 = bias1[col], b1 = bias1[col + 1];
            int pi = col >> 1;
            int r0 = m0 + wm * 32 + mt * 16 + g;
            if (r0 < N_NODES) {
                float2 v = make_float2(fmaxf(acc[mt][nb][0] + b0, 0.f), fmaxf(acc[mt][nb][1] + b1, 0.f));
                *(float2*)(g_x1 + (size_t)r0 * DIM + col) = v;
                if (r0 < NOUT2) {
                    g_X1h[(size_t)r0 * 64 + pi] = split_pack_hi(v);
                    g_X1l[(size_t)r0 * 64 + pi] = split_pack_lo(v);
                }
            }
            int r1 = r0 + 8;
            if (r1 < N_NODES) {
                float2 v = make_float2(fmaxf(acc[mt][nb][2] + b0, 0.f), fmaxf(acc[mt][nb][3] + b1, 0.f));
                *(float2*)(g_x1 + (size_t)r1 * DIM + col) = v;
                if (r1 < NOUT2) {
                    g_X1h[(size_t)r1 * 64 + pi] = split_pack_hi(v);
                    g_X1l[(size_t)r1 * 64 + pi] = split_pack_lo(v);
                }
            }
        }
    }
}

// GEMM2: x2 = [agg2 | x1] @ B2' + bias2
__global__ __launch_bounds__(256, 2) void k_gemm2_p(const float* __restrict__ bias2) {
    extern __shared__ char sm[];
    const uint32_t sbase = smem_u32(sm);
    const int tid = threadIdx.x, lane = tid & 31, wid = tid >> 5;
    const int wm = wid & 3, wn = wid >> 2;
    const int lrow = lane & 15, lk = lane >> 4;
    const int m0 = blockIdx.x * 128;

    float acc[2][8][4];
    #pragma unroll
    for (int i = 0; i < 2; i++)
        #pragma unroll
        for (int j = 0; j < 8; j++)
            #pragma unroll
            for (int c = 0; c < 4; c++) acc[i][j][c] = 0.f;

    STAGE_CHUNK(0, 0, g_A2h, g_A2l, g_X1h, g_X1l, g_BT2h, g_BT2l, NOUT2);
    for (int c = 0; c < 28; c++) {
        int s = c & 1;
        if (c < 27) {
            STAGE_CHUNK(c + 1, s ^ 1, g_A2h, g_A2l, g_X1h, g_X1l, g_BT2h, g_BT2l, NOUT2);
            CP_WAIT(1);
        } else {
            CP_WAIT(0);
        }
        __syncthreads();
        MMA_CHUNK(s);
        __syncthreads();
    }

    const int g = lane >> 2, tc = lane & 3;
    #pragma unroll
    for (int mt = 0; mt < 2; mt++) {
        #pragma unroll
        for (int nb = 0; nb < 8; nb++) {
            int col = wn * 64 + nb * 8 + tc * 2;
            float b0 = bias2[col], b1 = bias2[col + 1];
            int r0 = m0 + wm * 32 + mt * 16 + g;
            if (r0 < NOUT2)
                *(float2*)(g_x2 + (size_t)r0 * DIM + col) =
                    make_float2(acc[mt][nb][0] + b0, acc[mt][nb][1] + b1);
            int r1 = r0 + 8;
            if (r1 < NOUT2)
                *(float2*)(g_x2 + (size_t)r1 * DIM + col) =
                    make_float2(acc[mt][nb][2] + b0, acc[mt][nb][3] + b1);
        }
    }
}

// ---------------- scorer (HMMA) — minimal per-chunk loads + cp.async B ----------------
__global__ __launch_bounds__(256) void k_scorer_mma(const int* __restrict__ h_idx, const int* __restrict__ p_idx,
                                                    const float* __restrict__ sb1, const float* __restrict__ sw2,
                                                    const float* __restrict__ sb2, float* __restrict__ out) {
    extern __shared__ char sm[];
    __shared__ int sh_h[128], sh_p[128];
    uint32_t* Ah = (uint32_t*)sm;
    uint32_t* Al = (uint32_t*)(sm + TILE_BYTES);
    const uint32_t sAh = smem_u32(sm), sAl = sAh + TILE_BYTES, sBh = sAh + 2 * TILE_BYTES, sBl = sAh + 3 * TILE_BYTES;
    const int tid = threadIdx.x, lane = tid & 31, wid = tid >> 5;
    const int wm = wid & 3, wn = wid >> 2;
    const int lrow = lane & 15, lk = lane >> 4;
    const int pair0 = blockIdx.x * 128;

    for (int i = tid; i < 128; i += 256) {
        int pr = pair0 + i; if (pr >= NP) pr = NP - 1;
        sh_h[i] = h_idx[pr];
        sh_p[i] = N_HERB + p_idx[pr];
    }
    __syncthreads();

    float acc[2][8][4];
    #pragma unroll
    for (int i = 0; i < 2; i++)
        #pragma unroll
        for (int j = 0; j < 8; j++)
            #pragma unroll
            for (int c = 0; c < 4; c++) acc[i][j][c] = 0.f;

    for (int c = 0; c < 4; c++) {
        // stage B via cp.async: 128 rows x 16 x 16B = 2048 transfers
        for (int i = tid; i < 2048; i += 256) {
            int row = i >> 4, c16 = i & 15;
            uint32_t so = (uint32_t)(row * 272 + c16 * 16);
            cpa16(sBh + so, g_SW1h + (size_t)row * 256 + c * 64 + c16 * 4);
            cpa16(sBl + so, g_SW1l + (size_t)row * 256 + c * 64 + c16 * 4);
        }
        CP_COMMIT();
        // stage A: only the loads this chunk needs
        for (int i = tid; i < 128 * 64; i += 256) {
            int row = i >> 6, k2 = i & 63;
            float2 f;
            if (c == 0)      f = *(const float2*)(g_x2 + (size_t)sh_h[row] * DIM + k2 * 2);
            else if (c == 1) f = *(const float2*)(g_x2 + (size_t)sh_p[row] * DIM + k2 * 2);
            else {
                float2 h = *(const float2*)(g_x2 + (size_t)sh_h[row] * DIM + k2 * 2);
                float2 p = *(const float2*)(g_x2 + (size_t)sh_p[row] * DIM + k2 * 2);
                if (c == 2) f = make_float2(h.x * p.x, h.y * p.y);
                else        f = make_float2(fabsf(h.x - p.x), fabsf(h.y - p.y));
            }
            Ah[row * TSTR + k2] = split_pack_hi(f);
            Al[row * TSTR + k2] = split_pack_lo(f);
        }
        CP_WAIT(0);
        __syncthreads();
        #pragma unroll
        for (int kk8 = 0; kk8 < 8; kk8++) {
            uint32_t ah[2][4], al[2][4], bh[4][4], bl[4][4];
            #pragma unroll
            for (int mt = 0; mt < 2; mt++) {
                uint32_t off = (uint32_t)((wm * 32 + mt * 16 + lrow) * 272 + kk8 * 32 + lk * 16);
                ldm4(ah[mt], sAh + off);
                ldm4(al[mt], sAl + off);
            }
            #pragma unroll
            for (int nt = 0; nt < 4; nt++) {
                uint32_t off = (uint32_t)((wn * 64 + nt * 16 + lrow) * 272 + kk8 * 32 + lk * 16);
                ldm4(bh[nt], sBh + off);
                ldm4(bl[nt], sBl + off);
            }
            #pragma unroll
            for (int mt = 0; mt < 2; mt++)
                #pragma unroll
                for (int nt = 0; nt < 4; nt++) {
                    mma_bf16(acc[mt][2 * nt],     ah[mt], bh[nt][0], bh[nt][2]);
                    mma_bf16(acc[mt][2 * nt + 1], ah[mt], bh[nt][1], bh[nt][3]);
                    mma_bf16(acc[mt][2 * nt],     al[mt], bh[nt][0], bh[nt][2]);
                    mma_bf16(acc[mt][2 * nt + 1], al[mt], bh[nt][1], bh[nt][3]);
                    mma_bf16(acc[mt][2 * nt],     ah[mt], bl[nt][0], bl[nt][2]);
                    mma_bf16(acc[mt][2 * nt + 1], ah[mt], bl[nt][1], bl[nt][3]);
                }
        }
        __syncthreads();
    }

    __syncthreads();
    float* s_part = (float*)sm;              // [128][2]
    const int g = lane >> 2, tc = lane & 3;
    #pragma unroll
    for (int mt = 0; mt < 2; mt++) {
        float s0 = 0.f, s1 = 0.f;
        #pragma unroll
        for (int nb = 0; nb < 8; nb++) {
            int col = wn * 64 + nb * 8 + tc * 2;
            float w0 = sw2[col], w1 = sw2[col + 1];
            float bb0 = sb1[col], bb1 = sb1[col + 1];
            s0 += fmaxf(acc[mt][nb][0] + bb0, 0.f) * w0 + fmaxf(acc[mt][nb][1] + bb1, 0.f) * w1;
            s1 += fmaxf(acc[mt][nb][2] + bb0, 0.f) * w0 + fmaxf(acc[mt][nb][3] + bb1, 0.f) * w1;
        }
        s0 += __shfl_xor_sync(0xffffffff, s0, 1); s0 += __shfl_xor_sync(0xffffffff, s0, 2);
        s1 += __shfl_xor_sync(0xffffffff, s1, 1); s1 += __shfl_xor_sync(0xffffffff, s1, 2);
        if (tc == 0) {
            int r0 = wm * 32 + mt * 16 + g;
            s_part[r0 * 2 + wn] = s0;
            s_part[(r0 + 8) * 2 + wn] = s1;
        }
    }
    __syncthreads();
    if (tid < 128) {
        int pr = pair0 + tid;
        if (pr < NP) out[pr] = s_part[tid * 2] + s_part[tid * 2 + 1] + sb2[0];
    }
}

// ---------------- launch ----------------
extern "C" void kernel_launch(void* const* d_in, const int* in_sizes, int n_in,
                              void* d_out, int out_size) {
    const int*   edge_index = (const int*)d_in[0];
    const int*   edge_type  = (const int*)d_in[1];
    const int*   h_idx      = (const int*)d_in[2];
    const int*   p_idx      = (const int*)d_in[3];
    const float* node_emb   = (const float*)d_in[4];
    const float* basis1 = (const float*)d_in[5];
    const float* comp1  = (const float*)d_in[6];
    const float* root1  = (const float*)d_in[7];
    const float* bias1  = (const float*)d_in[8];
    const float* basis2 = (const float*)d_in[9];
    const float* comp2  = (const float*)d_in[10];
    const float* root2  = (const float*)d_in[11];
    const float* bias2  = (const float*)d_in[12];
    const float* sw1 = (const float*)d_in[13];
    const float* sb1 = (const float*)d_in[14];
    const float* sw2 = (const float*)d_in[15];
    const float* sb2 = (const float*)d_in[16];
    float* out = (float*)d_out;

    cudaFuncSetAttribute(k_gemm1_p, cudaFuncAttributeMaxDynamicSharedMemorySize, PSMEM);
    cudaFuncSetAttribute(k_gemm2_p, cudaFuncAttributeMaxDynamicSharedMemorySize, PSMEM);
    cudaFuncSetAttribute(k_scorer_mma, cudaFuncAttributeMaxDynamicSharedMemorySize, 4 * TILE_BYTES);

    // side stream + events (created once; host objects, not device memory)
    static cudaStream_t s1 = nullptr;
    static cudaEvent_t evFork = nullptr, evJoin = nullptr;
    if (s1 == nullptr) {
        cudaStreamCreateWithFlags(&s1, cudaStreamNonBlocking);
        cudaEventCreateWithFlags(&evFork, cudaEventDisableTiming);
        cudaEventCreateWithFlags(&evJoin, cudaEventDisableTiming);
    }

    // fork: builds on s1, CSR+gather1 on main (legacy) stream
    cudaEventRecord(evFork, 0);
    cudaStreamWaitEvent(s1, evFork, 0);
    k_build_all<<<(BLD_EMB + 255) / 256, 256, 0, s1>>>(basis1, comp1, root1,
                                                       basis2, comp2, root2,
                                                       sw1, node_emb);

    int* cnt_ptr = nullptr;
    cudaGetSymbolAddress((void**)&cnt_ptr, g_cnt);
    cudaMemsetAsync(cnt_ptr, 0, NSEG1 * sizeof(int), 0);
    k_count<<<(NE + 255) / 256, 256>>>(edge_index, edge_type);
    k_scan_a<<<NBLK, SCAN_BLK>>>();
    k_scan_c<<<NBLK, SCAN_BLK>>>();
    k_fill<<<(NE + 255) / 256, 256>>>(edge_index, edge_type);
    k_gather1<<<(NSEG1 * 32 + 255) / 256, 256>>>(node_emb);

    // join: GEMMs need the built weights
    cudaEventRecord(evJoin, s1);
    cudaStreamWaitEvent(0, evJoin, 0);

    k_gemm1_p<<<(N_NODES + 127) / 128, 256, PSMEM>>>(bias1);
    k_gather2<<<(NSEG2 * 32 + 255) / 256, 256>>>();
    k_gemm2_p<<<(NOUT2 + 127) / 128, 256, PSMEM>>>(bias2);
    k_scorer_mma<<<(NP + 127) / 128, 256, 4 * TILE_BYTES>>>(h_idx, p_idx, sb1, sw2, sb2, out);
}

// round 12
// speedup vs baseline: 1.6936x; 1.0785x over previous
#include <cuda_runtime.h>
#include <cuda_bf16.h>
#include <cstdint>

#define N_NODES 60000
#define N_HERB  5000
#define NOUT2   25000
#define DIM     128
#define NREL    6
#define NB      30
#define NE      600000
#define NP      40000
#define NSEG1   (N_NODES * NREL)   // 360000
#define NSEG2   (NOUT2 * NREL)     // 150000
#define SCAN_BLK 1024
#define NBLK    ((NSEG1 + SCAN_BLK - 1) / SCAN_BLK)   // 352

// ---------------- scratch ----------------
__device__ uint32_t g_A1h[(size_t)NSEG1 * 64], g_A1l[(size_t)NSEG1 * 64];
__device__ uint32_t g_A2h[(size_t)NSEG2 * 64], g_A2l[(size_t)NSEG2 * 64];
__device__ uint32_t g_Eh[(size_t)N_NODES * 64], g_El[(size_t)N_NODES * 64];
__device__ uint32_t g_X1h[(size_t)NOUT2 * 64], g_X1l[(size_t)NOUT2 * 64];
__device__ float g_x1[(size_t)N_NODES * DIM];
__device__ float g_x2[(size_t)NOUT2 * DIM];
__device__ int   g_cnt[NSEG1];
__device__ int   g_off[NSEG1 + 1];
__device__ int   g_cursor[NSEG1];
__device__ int   g_esrc[NE];
__device__ int   g_bsum[NBLK];
__device__ uint32_t g_BT1h[128 * 448], g_BT1l[128 * 448];
__device__ uint32_t g_BT2h[128 * 448], g_BT2l[128 * 448];
__device__ uint32_t g_SW1h[128 * 256], g_SW1l[128 * 256];

// ---------------- helpers ----------------
__device__ __forceinline__ uint32_t smem_u32(const void* p) {
    uint32_t a;
    asm("{ .reg .u64 t; cvta.to.shared.u64 t, %1; cvt.u32.u64 %0, t; }" : "=r"(a) : "l"(p));
    return a;
}
__device__ __forceinline__ void ldm4(uint32_t* r, uint32_t addr) {
    asm volatile("ldmatrix.sync.aligned.m8n8.x4.shared.b16 {%0,%1,%2,%3}, [%4];"
        : "=r"(r[0]), "=r"(r[1]), "=r"(r[2]), "=r"(r[3]) : "r"(addr));
}
__device__ __forceinline__ void mma_bf16(float* d, const uint32_t* a, uint32_t b0, uint32_t b1) {
    asm volatile("mma.sync.aligned.m16n8k16.row.col.f32.bf16.bf16.f32 "
        "{%0,%1,%2,%3}, {%4,%5,%6,%7}, {%8,%9}, {%0,%1,%2,%3};"
        : "+f"(d[0]), "+f"(d[1]), "+f"(d[2]), "+f"(d[3])
        : "r"(a[0]), "r"(a[1]), "r"(a[2]), "r"(a[3]), "r"(b0), "r"(b1));
}
__device__ __forceinline__ uint32_t split_pack_hi(float2 f) {
    __nv_bfloat162 h;
    h.x = __float2bfloat16_rn(f.x); h.y = __float2bfloat16_rn(f.y);
    return *(uint32_t*)&h;
}
__device__ __forceinline__ uint32_t split_pack_lo(float2 f) {
    __nv_bfloat16 hx = __float2bfloat16_rn(f.x), hy = __float2bfloat16_rn(f.y);
    __nv_bfloat162 l;
    l.x = __float2bfloat16_rn(f.x - __bfloat162float(hx));
    l.y = __float2bfloat16_rn(f.y - __bfloat162float(hy));
    return *(uint32_t*)&l;
}
__device__ __forceinline__ void cpa16(uint32_t saddr, const void* g) {
    asm volatile("cp.async.cg.shared.global [%0], [%1], 16;" :: "r"(saddr), "l"(g));
}
#define CP_COMMIT() asm volatile("cp.async.commit_group;" ::: "memory")
#define CP_WAIT(n)  asm volatile("cp.async.wait_group %0;" :: "n"(n) : "memory")

// pipelined GEMM tile: 128 rows x 16 u32 (K=32 bf16), padded stride 20 u32 (80 B)
#define PSTR 20
#define PTILE (128 * PSTR * 4)    // 10240 B
#define PSMEM (8 * PTILE)         // 81920 B -> 2 CTAs/SM
// scorer geometry: K=64 chunks, 128 rows x 32 u32, stride 36 u32 (144 B)
#define SSTR 36
#define STILE (128 * SSTR * 4)    // 18432 B
#define SSMEM (4 * STILE)         // 73728 B -> 2 CTAs/SM

// ---------------- merged weight/emb build (one kernel, range-dispatched) ----------------
#define BLD_W1   (128 * 448)                 // 57344
#define BLD_W2   (BLD_W1 + 128 * 448)        // 114688
#define BLD_SW   (BLD_W2 + 128 * 256)        // 147456
#define BLD_EMB  (BLD_SW + N_NODES * 32)     // emb: float4 per thread
__global__ void k_build_all(const float* __restrict__ basis1, const float* __restrict__ comp1,
                            const float* __restrict__ root1,
                            const float* __restrict__ basis2, const float* __restrict__ comp2,
                            const float* __restrict__ root2,
                            const float* __restrict__ sw1, const float* __restrict__ X) {
    int gid = blockIdx.x * blockDim.x + threadIdx.x;
    if (gid >= BLD_EMB) return;
    if (gid < BLD_W2) {
        const float* basis = (gid < BLD_W1) ? basis1 : basis2;
        const float* comp  = (gid < BLD_W1) ? comp1 : comp2;
        const float* root  = (gid < BLD_W1) ? root1 : root2;
        uint32_t* dh = (gid < BLD_W1) ? g_BT1h : g_BT2h;
        uint32_t* dl = (gid < BLD_W1) ? g_BT1l : g_BT2l;
        int idx = (gid < BLD_W1) ? gid : gid - BLD_W1;
        int o = idx / 448, j = idx % 448, k0 = j * 2;
        float w0, w1;
        if (k0 < 768) {
            int r = k0 >> 7, d0 = k0 & 127;
            w0 = 0.f; w1 = 0.f;
            #pragma unroll
            for (int b = 0; b < NB; b++) {
                float cc = comp[r * NB + b];
                w0 += cc * basis[b * 16384 + d0 * 128 + o];
                w1 += cc * basis[b * 16384 + (d0 + 1) * 128 + o];
            }
        } else {
            int d0 = k0 - 768;
            w0 = root[d0 * 128 + o]; w1 = root[(d0 + 1) * 128 + o];
        }
        float2 f = make_float2(w0, w1);
        dh[idx] = split_pack_hi(f);
        dl[idx] = split_pack_lo(f);
    } else if (gid < BLD_SW) {
        int idx = gid - BLD_W2;
        int o = idx >> 8, j = idx & 255, k0 = j * 2;
        float2 f = make_float2(sw1[k0 * 128 + o], sw1[(k0 + 1) * 128 + o]);
        g_SW1h[idx] = split_pack_hi(f);
        g_SW1l[idx] = split_pack_lo(f);
    } else {
        int idx = gid - BLD_SW;     // 0 .. N_NODES*32
        float4 f = ((const float4*)X)[idx];
        float2 f01 = make_float2(f.x, f.y), f23 = make_float2(f.z, f.w);
        *(uint2*)(g_Eh + (size_t)idx * 2) = make_uint2(split_pack_hi(f01), split_pack_hi(f23));
        *(uint2*)(g_El + (size_t)idx * 2) = make_uint2(split_pack_lo(f01), split_pack_lo(f23));
    }
}

// ---------------- CSR build ----------------
__global__ void k_count(const int* __restrict__ ei, const int* __restrict__ et) {
    int e = blockIdx.x * blockDim.x + threadIdx.x;
    if (e < NE) atomicAdd(&g_cnt[ei[NE + e] * NREL + et[e]], 1);
}
__global__ __launch_bounds__(SCAN_BLK) void k_scan_a() {
    __shared__ int sm[SCAN_BLK];
    int t = threadIdx.x;
    int gid = blockIdx.x * SCAN_BLK + t;
    int v = (gid < NSEG1) ? g_cnt[gid] : 0;
    sm[t] = v;
    __syncthreads();
    for (int d = 1; d < SCAN_BLK; d <<= 1) {
        int x = (t >= d) ? sm[t - d] : 0;
        __syncthreads();
        sm[t] += x;
        __syncthreads();
    }
    if (gid < NSEG1) g_off[gid] = sm[t] - v;
    if (t == SCAN_BLK - 1) g_bsum[blockIdx.x] = sm[t];
}
__global__ __launch_bounds__(SCAN_BLK) void k_scan_c() {
    __shared__ int red[SCAN_BLK];
    int t = threadIdx.x;
    red[t] = (t < (int)blockIdx.x && t < NBLK) ? g_bsum[t] : 0;
    __syncthreads();
    for (int d = SCAN_BLK / 2; d > 0; d >>= 1) {
        if (t < d) red[t] += red[t + d];
        __syncthreads();
    }
    int pre = red[0];
    int gid = blockIdx.x * SCAN_BLK + t;
    if (gid < NSEG1) {
        int o = g_off[gid] + pre;
        g_off[gid] = o;
        g_cursor[gid] = o;
    }
    if (gid == 0) g_off[NSEG1] = NE;
}
__global__ void k_fill(const int* __restrict__ ei, const int* __restrict__ et) {
    int e = blockIdx.x * blockDim.x + threadIdx.x;
    if (e < NE) {
        int seg = ei[NE + e] * NREL + et[e];
        int pos = atomicAdd(&g_cursor[seg], 1);
        g_esrc[pos] = ei[e];
    }
}

// ---------------- gathers ----------------
__global__ __launch_bounds__(256) void k_gather1(const float* __restrict__ X) {
    int w = (int)((blockIdx.x * 256u + threadIdx.x) >> 5);
    if (w >= NSEG1) return;
    int lane = threadIdx.x & 31;
    int s0 = g_off[w], s1 = g_off[w + 1];
    float4 acc = make_float4(0.f, 0.f, 0.f, 0.f);
    for (int e = s0; e < s1; e++) {
        const float4 v = *(const float4*)(X + (size_t)g_esrc[e] * DIM + lane * 4);
        acc.x += v.x; acc.y += v.y; acc.z += v.z; acc.w += v.w;
    }
    float sc = (s1 > s0) ? 1.f / (float)(s1 - s0) : 0.f;
    float2 f01 = make_float2(acc.x * sc, acc.y * sc);
    float2 f23 = make_float2(acc.z * sc, acc.w * sc);
    size_t base = (size_t)w * 64 + lane * 2;
    *(uint2*)(g_A1h + base) = make_uint2(split_pack_hi(f01), split_pack_hi(f23));
    *(uint2*)(g_A1l + base) = make_uint2(split_pack_lo(f01), split_pack_lo(f23));
}
__global__ __launch_bounds__(256) void k_gather2() {
    int w = (int)((blockIdx.x * 256u + threadIdx.x) >> 5);
    if (w >= NSEG2) return;
    int lane = threadIdx.x & 31;
    int s0 = g_off[w], s1 = g_off[w + 1];
    float4 acc = make_float4(0.f, 0.f, 0.f, 0.f);
    for (int e = s0; e < s1; e++) {
        const float4 v = *(const float4*)(g_x1 + (size_t)g_esrc[e] * DIM + lane * 4);
        acc.x += v.x; acc.y += v.y; acc.z += v.z; acc.w += v.w;
    }
    float sc = (s1 > s0) ? 1.f / (float)(s1 - s0) : 0.f;
    float2 f01 = make_float2(acc.x * sc, acc.y * sc);
    float2 f23 = make_float2(acc.z * sc, acc.w * sc);
    size_t base = (size_t)w * 64 + lane * 2;
    *(uint2*)(g_A2h + base) = make_uint2(split_pack_hi(f01), split_pack_hi(f23));
    *(uint2*)(g_A2l + base) = make_uint2(split_pack_lo(f01), split_pack_lo(f23));
}

// ---------------- pipelined HMMA GEMM core (K=32 chunks, 28 chunks) ----------------
#define STAGE_CHUNK(c_, s_, AGGH, AGGL, ROOTH, ROOTL, BTH, BTL, NLIM)                         \
    do {                                                                                      \
        int cc = (c_);                                                                        \
        uint32_t sb0 = sbase + (uint32_t)((s_) * 4) * PTILE;                                  \
        _Pragma("unroll")                                                                     \
        for (int k = 0; k < 2; k++) {                                                         \
            int idx = tid + k * 256;                                                          \
            int row = idx >> 2, c16 = idx & 3;                                                \
            int grow = m0 + row; if (grow >= (NLIM)) grow = (NLIM) - 1;                       \
            const uint32_t *srch, *srcl;                                                      \
            if (cc < 24) {                                                                    \
                size_t sgb = ((size_t)grow * 6 + (cc >> 2)) * 64 + (cc & 3) * 16;             \
                srch = (AGGH) + sgb; srcl = (AGGL) + sgb;                                     \
            } else {                                                                          \
                size_t sgb = (size_t)grow * 64 + (cc - 24) * 16;                              \
                srch = (ROOTH) + sgb; srcl = (ROOTL) + sgb;                                   \
            }                                                                                 \
            uint32_t so = (uint32_t)(row * 80 + c16 * 16);                                    \
            cpa16(sb0 + 0 * PTILE + so, srch + c16 * 4);                                      \
            cpa16(sb0 + 1 * PTILE + so, srcl + c16 * 4);                                      \
            const uint32_t* bh = (BTH) + (size_t)row * 448 + cc * 16;                         \
            const uint32_t* bl = (BTL) + (size_t)row * 448 + cc * 16;                         \
            cpa16(sb0 + 2 * PTILE + so, bh + c16 * 4);                                        \
            cpa16(sb0 + 3 * PTILE + so, bl + c16 * 4);                                        \
        }                                                                                     \
        CP_COMMIT();                                                                          \
    } while (0)

#define MMA_CHUNK(s_)                                                                         \
    do {                                                                                      \
        uint32_t sb0 = sbase + (uint32_t)((s_) * 4) * PTILE;                                  \
        _Pragma("unroll")                                                                     \
        for (int kk = 0; kk < 2; kk++) {                                                      \
            uint32_t ah[2][4], al[2][4], bh[4][4], bl[4][4];                                  \
            _Pragma("unroll")                                                                 \
            for (int mt = 0; mt < 2; mt++) {                                                  \
                uint32_t off = (uint32_t)((wm * 32 + mt * 16 + lrow) * 80 + kk * 32 + lk * 16); \
                ldm4(ah[mt], sb0 + 0 * PTILE + off);                                          \
                ldm4(al[mt], sb0 + 1 * PTILE + off);                                          \
            }                                                                                 \
            _Pragma("unroll")                                                                 \
            for (int nt = 0; nt < 4; nt++) {                                                  \
                uint32_t off = (uint32_t)((wn * 64 + nt * 16 + lrow) * 80 + kk * 32 + lk * 16); \
                ldm4(bh[nt], sb0 + 2 * PTILE + off);                                          \
                ldm4(bl[nt], sb0 + 3 * PTILE + off);                                          \
            }                                                                                 \
            _Pragma("unroll")                                                                 \
            for (int mt = 0; mt < 2; mt++)                                                    \
                _Pragma("unroll")                                                             \
                for (int nt = 0; nt < 4; nt++) {                                              \
                    mma_bf16(acc[mt][2 * nt],     ah[mt], bh[nt][0], bh[nt][2]);              \
                    mma_bf16(acc[mt][2 * nt + 1], ah[mt], bh[nt][1], bh[nt][3]);              \
                    mma_bf16(acc[mt][2 * nt],     al[mt], bh[nt][0], bh[nt][2]);              \
                    mma_bf16(acc[mt][2 * nt + 1], al[mt], bh[nt][1], bh[nt][3]);              \
                    mma_bf16(acc[mt][2 * nt],     ah[mt], bl[nt][0], bl[nt][2]);              \
                    mma_bf16(acc[mt][2 * nt + 1], ah[mt], bl[nt][1], bl[nt][3]);              \
                }                                                                             \
        }                                                                                     \
    } while (0)

// GEMM1: x1 = relu([agg1 | emb] @ B1' + bias1); split copy only for rows < NOUT2
__global__ __launch_bounds__(256, 2) void k_gemm1_p(const float* __restrict__ bias1) {
    extern __shared__ char sm[];
    const uint32_t sbase = smem_u32(sm);
    const int tid = threadIdx.x, lane = tid & 31, wid = tid >> 5;
    const int wm = wid & 3, wn = wid >> 2;
    const int lrow = lane & 15, lk = lane >> 4;
    const int m0 = blockIdx.x * 128;

    float acc[2][8][4];
    #pragma unroll
    for (int i = 0; i < 2; i++)
        #pragma unroll
        for (int j = 0; j < 8; j++)
            #pragma unroll
            for (int c = 0; c < 4; c++) acc[i][j][c] = 0.f;

    STAGE_CHUNK(0, 0, g_A1h, g_A1l, g_Eh, g_El, g_BT1h, g_BT1l, N_NODES);
    for (int c = 0; c < 28; c++) {
        int s = c & 1;
        if (c < 27) {
            STAGE_CHUNK(c + 1, s ^ 1, g_A1h, g_A1l, g_Eh, g_El, g_BT1h, g_BT1l, N_NODES);
            CP_WAIT(1);
        } else {
            CP_WAIT(0);
        }
        __syncthreads();
        MMA_CHUNK(s);
        __syncthreads();
    }

    const int g = lane >> 2, tc = lane & 3;
    #pragma unroll
    for (int mt = 0; mt < 2; mt++) {
        #pragma unroll
        for (int nb = 0; nb < 8; nb++) {
            int col = wn * 64 + nb * 8 + tc * 2;
            float b0 = bias1[col], b1 = bias1[col + 1];
            int pi = col >> 1;
            int r0 = m0 + wm * 32 + mt * 16 + g;
            if (r0 < N_NODES) {
                float2 v = make_float2(fmaxf(acc[mt][nb][0] + b0, 0.f), fmaxf(acc[mt][nb][1] + b1, 0.f));
                *(float2*)(g_x1 + (size_t)r0 * DIM + col) = v;
                if (r0 < NOUT2) {
                    g_X1h[(size_t)r0 * 64 + pi] = split_pack_hi(v);
                    g_X1l[(size_t)r0 * 64 + pi] = split_pack_lo(v);
                }
            }
            int r1 = r0 + 8;
            if (r1 < N_NODES) {
                float2 v = make_float2(fmaxf(acc[mt][nb][2] + b0, 0.f), fmaxf(acc[mt][nb][3] + b1, 0.f));
                *(float2*)(g_x1 + (size_t)r1 * DIM + col) = v;
                if (r1 < NOUT2) {
                    g_X1h[(size_t)r1 * 64 + pi] = split_pack_hi(v);
                    g_X1l[(size_t)r1 * 64 + pi] = split_pack_lo(v);
                }
            }
        }
    }
}

// GEMM2: x2 = [agg2 | x1] @ B2' + bias2
__global__ __launch_bounds__(256, 2) void k_gemm2_p(const float* __restrict__ bias2) {
    extern __shared__ char sm[];
    const uint32_t sbase = smem_u32(sm);
    const int tid = threadIdx.x, lane = tid & 31, wid = tid >> 5;
    const int wm = wid & 3, wn = wid >> 2;
    const int lrow = lane & 15, lk = lane >> 4;
    const int m0 = blockIdx.x * 128;

    float acc[2][8][4];
    #pragma unroll
    for (int i = 0; i < 2; i++)
        #pragma unroll
        for (int j = 0; j < 8; j++)
            #pragma unroll
            for (int c = 0; c < 4; c++) acc[i][j][c] = 0.f;

    STAGE_CHUNK(0, 0, g_A2h, g_A2l, g_X1h, g_X1l, g_BT2h, g_BT2l, NOUT2);
    for (int c = 0; c < 28; c++) {
        int s = c & 1;
        if (c < 27) {
            STAGE_CHUNK(c + 1, s ^ 1, g_A2h, g_A2l, g_X1h, g_X1l, g_BT2h, g_BT2l, NOUT2);
            CP_WAIT(1);
        } else {
            CP_WAIT(0);
        }
        __syncthreads();
        MMA_CHUNK(s);
        __syncthreads();
    }

    const int g = lane >> 2, tc = lane & 3;
    #pragma unroll
    for (int mt = 0; mt < 2; mt++) {
        #pragma unroll
        for (int nb = 0; nb < 8; nb++) {
            int col = wn * 64 + nb * 8 + tc * 2;
            float b0 = bias2[col], b1 = bias2[col + 1];
            int r0 = m0 + wm * 32 + mt * 16 + g;
            if (r0 < NOUT2)
                *(float2*)(g_x2 + (size_t)r0 * DIM + col) =
                    make_float2(acc[mt][nb][0] + b0, acc[mt][nb][1] + b1);
            int r1 = r0 + 8;
            if (r1 < NOUT2)
                *(float2*)(g_x2 + (size_t)r1 * DIM + col) =
                    make_float2(acc[mt][nb][2] + b0, acc[mt][nb][3] + b1);
        }
    }
}

// ---------------- scorer (HMMA): K=64 chunks, 2 CTAs/SM ----------------
__global__ __launch_bounds__(256, 2) void k_scorer_mma(const int* __restrict__ h_idx, const int* __restrict__ p_idx,
                                                       const float* __restrict__ sb1, const float* __restrict__ sw2,
                                                       const float* __restrict__ sb2, float* __restrict__ out) {
    extern __shared__ char sm[];
    __shared__ int sh_h[128], sh_p[128];
    uint32_t* Ah = (uint32_t*)sm;
    uint32_t* Al = (uint32_t*)(sm + STILE);
    const uint32_t sAh = smem_u32(sm), sAl = sAh + STILE, sBh = sAh + 2 * STILE, sBl = sAh + 3 * STILE;
    const int tid = threadIdx.x, lane = tid & 31, wid = tid >> 5;
    const int wm = wid & 3, wn = wid >> 2;
    const int lrow = lane & 15, lk = lane >> 4;
    const int pair0 = blockIdx.x * 128;

    for (int i = tid; i < 128; i += 256) {
        int pr = pair0 + i; if (pr >= NP) pr = NP - 1;
        sh_h[i] = h_idx[pr];
        sh_p[i] = N_HERB + p_idx[pr];
    }
    __syncthreads();

    float acc[2][8][4];
    #pragma unroll
    for (int i = 0; i < 2; i++)
        #pragma unroll
        for (int j = 0; j < 8; j++)
            #pragma unroll
            for (int c = 0; c < 4; c++) acc[i][j][c] = 0.f;

    for (int c = 0; c < 8; c++) {
        // stage B via cp.async: 128 rows x 8 x 16B
        for (int i = tid; i < 1024; i += 256) {
            int row = i >> 3, c16 = i & 7;
            uint32_t so = (uint32_t)(row * 144 + c16 * 16);
            cpa16(sBh + so, g_SW1h + (size_t)row * 256 + c * 32 + c16 * 4);
            cpa16(sBl + so, g_SW1l + (size_t)row * 256 + c * 32 + c16 * 4);
        }
        CP_COMMIT();
        // stage A: 64-dim feature slice; c 0,1:h  2,3:p  4,5:h*p  6,7:|h-p|
        for (int i = tid; i < 128 * 32; i += 256) {
            int row = i >> 5, k2 = i & 31;
            int pi = ((c & 1) << 5) + k2;   // pair index within 128-dim row
            const float2* hr = (const float2*)(g_x2 + (size_t)sh_h[row] * DIM);
            const float2* pr = (const float2*)(g_x2 + (size_t)sh_p[row] * DIM);
            float2 f;
            if (c < 2)      f = hr[pi];
            else if (c < 4) f = pr[pi];
            else if (c < 6) { float2 h = hr[pi], p = pr[pi]; f = make_float2(h.x * p.x, h.y * p.y); }
            else            { float2 h = hr[pi], p = pr[pi]; f = make_float2(fabsf(h.x - p.x), fabsf(h.y - p.y)); }
            Ah[row * SSTR + k2] = split_pack_hi(f);
            Al[row * SSTR + k2] = split_pack_lo(f);
        }
        CP_WAIT(0);
        __syncthreads();
        #pragma unroll
        for (int kk = 0; kk < 4; kk++) {
            uint32_t ah[2][4], al[2][4], bh[4][4], bl[4][4];
            #pragma unroll
            for (int mt = 0; mt < 2; mt++) {
                uint32_t off = (uint32_t)((wm * 32 + mt * 16 + lrow) * 144 + kk * 32 + lk * 16);
                ldm4(ah[mt], sAh + off);
                ldm4(al[mt], sAl + off);
            }
            #pragma unroll
            for (int nt = 0; nt < 4; nt++) {
                uint32_t off = (uint32_t)((wn * 64 + nt * 16 + lrow) * 144 + kk * 32 + lk * 16);
                ldm4(bh[nt], sBh + off);
                ldm4(bl[nt], sBl + off);
            }
            #pragma unroll
            for (int mt = 0; mt < 2; mt++)
                #pragma unroll
                for (int nt = 0; nt < 4; nt++) {
                    mma_bf16(acc[mt][2 * nt],     ah[mt], bh[nt][0], bh[nt][2]);
                    mma_bf16(acc[mt][2 * nt + 1], ah[mt], bh[nt][1], bh[nt][3]);
                    mma_bf16(acc[mt][2 * nt],     al[mt], bh[nt][0], bh[nt][2]);
                    mma_bf16(acc[mt][2 * nt + 1], al[mt], bh[nt][1], bh[nt][3]);
                    mma_bf16(acc[mt][2 * nt],     ah[mt], bl[nt][0], bl[nt][2]);
                    mma_bf16(acc[mt][2 * nt + 1], ah[mt], bl[nt][1], bl[nt][3]);
                }
        }
        __syncthreads();
    }

    __syncthreads();
    float* s_part = (float*)sm;              // [128][2]
    const int g = lane >> 2, tc = lane & 3;
    #pragma unroll
    for (int mt = 0; mt < 2; mt++) {
        float s0 = 0.f, s1 = 0.f;
        #pragma unroll
        for (int nb = 0; nb < 8; nb++) {
            int col = wn * 64 + nb * 8 + tc * 2;
            float w0 = sw2[col], w1 = sw2[col + 1];
            float bb0 = sb1[col], bb1 = sb1[col + 1];
            s0 += fmaxf(acc[mt][nb][0] + bb0, 0.f) * w0 + fmaxf(acc[mt][nb][1] + bb1, 0.f) * w1;
            s1 += fmaxf(acc[mt][nb][2] + bb0, 0.f) * w0 + fmaxf(acc[mt][nb][3] + bb1, 0.f) * w1;
        }
        s0 += __shfl_xor_sync(0xffffffff, s0, 1); s0 += __shfl_xor_sync(0xffffffff, s0, 2);
        s1 += __shfl_xor_sync(0xffffffff, s1, 1); s1 += __shfl_xor_sync(0xffffffff, s1, 2);
        if (tc == 0) {
            int r0 = wm * 32 + mt * 16 + g;
            s_part[r0 * 2 + wn] = s0;
            s_part[(r0 + 8) * 2 + wn] = s1;
        }
    }
    __syncthreads();
    if (tid < 128) {
        int pr = pair0 + tid;
        if (pr < NP) out[pr] = s_part[tid * 2] + s_part[tid * 2 + 1] + sb2[0];
    }
}

// ---------------- launch ----------------
extern "C" void kernel_launch(void* const* d_in, const int* in_sizes, int n_in,
                              void* d_out, int out_size) {
    const int*   edge_index = (const int*)d_in[0];
    const int*   edge_type  = (const int*)d_in[1];
    const int*   h_idx      = (const int*)d_in[2];
    const int*   p_idx      = (const int*)d_in[3];
    const float* node_emb   = (const float*)d_in[4];
    const float* basis1 = (const float*)d_in[5];
    const float* comp1  = (const float*)d_in[6];
    const float* root1  = (const float*)d_in[7];
    const float* bias1  = (const float*)d_in[8];
    const float* basis2 = (const float*)d_in[9];
    const float* comp2  = (const float*)d_in[10];
    const float* root2  = (const float*)d_in[11];
    const float* bias2  = (const float*)d_in[12];
    const float* sw1 = (const float*)d_in[13];
    const float* sb1 = (const float*)d_in[14];
    const float* sw2 = (const float*)d_in[15];
    const float* sb2 = (const float*)d_in[16];
    float* out = (float*)d_out;

    cudaFuncSetAttribute(k_gemm1_p, cudaFuncAttributeMaxDynamicSharedMemorySize, PSMEM);
    cudaFuncSetAttribute(k_gemm2_p, cudaFuncAttributeMaxDynamicSharedMemorySize, PSMEM);
    cudaFuncSetAttribute(k_scorer_mma, cudaFuncAttributeMaxDynamicSharedMemorySize, SSMEM);

    static cudaStream_t s1 = nullptr;
    static cudaEvent_t evFork = nullptr, evJoin = nullptr;
    if (s1 == nullptr) {
        cudaStreamCreateWithFlags(&s1, cudaStreamNonBlocking);
        cudaEventCreateWithFlags(&evFork, cudaEventDisableTiming);
        cudaEventCreateWithFlags(&evJoin, cudaEventDisableTiming);
    }

    // fork: builds on s1, CSR+gather1 on main stream
    cudaEventRecord(evFork, 0);
    cudaStreamWaitEvent(s1, evFork, 0);
    k_build_all<<<(BLD_EMB + 255) / 256, 256, 0, s1>>>(basis1, comp1, root1,
                                                       basis2, comp2, root2,
                                                       sw1, node_emb);

    int* cnt_ptr = nullptr;
    cudaGetSymbolAddress((void**)&cnt_ptr, g_cnt);
    cudaMemsetAsync(cnt_ptr, 0, NSEG1 * sizeof(int), 0);
    k_count<<<(NE + 255) / 256, 256>>>(edge_index, edge_type);
    k_scan_a<<<NBLK, SCAN_BLK>>>();
    k_scan_c<<<NBLK, SCAN_BLK>>>();
    k_fill<<<(NE + 255) / 256, 256>>>(edge_index, edge_type);
    k_gather1<<<(NSEG1 * 32 + 255) / 256, 256>>>(node_emb);

    // join: GEMMs need the built weights
    cudaEventRecord(evJoin, s1);
    cudaStreamWaitEvent(0, evJoin, 0);

    k_gemm1_p<<<(N_NODES + 127) / 128, 256, PSMEM>>>(bias1);
    k_gather2<<<(NSEG2 * 32 + 255) / 256, 256>>>();
    k_gemm2_p<<<(NOUT2 + 127) / 128, 256, PSMEM>>>(bias2);
    k_scorer_mma<<<(NP + 127) / 128, 256, SSMEM>>>(h_idx, p_idx, sb1, sw2, sb2, out);
}

// round 13
// speedup vs baseline: 1.7213x; 1.0163x over previous
#include <cuda_runtime.h>
#include <cuda_bf16.h>
#include <cstdint>

#define N_NODES 60000
#define N_HERB  5000
#define NOUT2   25000
#define DIM     128
#define NREL    6
#define NB      30
#define NE      600000
#define NP      40000
#define NSEG1   (N_NODES * NREL)   // 360000
#define NSEG2   (NOUT2 * NREL)     // 150000
#define SCAN_BLK 1024
#define NBLK    ((NSEG1 + SCAN_BLK - 1) / SCAN_BLK)   // 352

// phase-split points (row-aligned to 128-row GEMM blocks)
#define G1_BLKA 235
#define R1SPLIT (G1_BLKA * 128)        // 30080
#define G1_BLKB 234
#define S1A     (R1SPLIT * NREL)       // 180480
#define G2_BLKA 98
#define R2SPLIT (G2_BLKA * 128)        // 12544
#define G2_BLKB 98
#define S2A     (R2SPLIT * NREL)       // 75264

// ---------------- scratch ----------------
__device__ uint32_t g_A1h[(size_t)NSEG1 * 64], g_A1l[(size_t)NSEG1 * 64];
__device__ uint32_t g_A2h[(size_t)NSEG2 * 64], g_A2l[(size_t)NSEG2 * 64];
__device__ uint32_t g_Eh[(size_t)N_NODES * 64], g_El[(size_t)N_NODES * 64];
__device__ uint32_t g_X1h[(size_t)NOUT2 * 64], g_X1l[(size_t)NOUT2 * 64];
__device__ float g_x1[(size_t)N_NODES * DIM];
__device__ float g_x2[(size_t)NOUT2 * DIM];
__device__ int   g_cnt[NSEG1];
__device__ int   g_off[NSEG1 + 1];
__device__ int   g_cursor[NSEG1];
__device__ int   g_esrc[NE];
__device__ int   g_bsum[NBLK];
__device__ uint32_t g_BT1h[128 * 448], g_BT1l[128 * 448];
__device__ uint32_t g_BT2h[128 * 448], g_BT2l[128 * 448];
__device__ uint32_t g_SW1h[128 * 256], g_SW1l[128 * 256];

// ---------------- helpers ----------------
__device__ __forceinline__ uint32_t smem_u32(const void* p) {
    uint32_t a;
    asm("{ .reg .u64 t; cvta.to.shared.u64 t, %1; cvt.u32.u64 %0, t; }" : "=r"(a) : "l"(p));
    return a;
}
__device__ __forceinline__ void ldm4(uint32_t* r, uint32_t addr) {
    asm volatile("ldmatrix.sync.aligned.m8n8.x4.shared.b16 {%0,%1,%2,%3}, [%4];"
        : "=r"(r[0]), "=r"(r[1]), "=r"(r[2]), "=r"(r[3]) : "r"(addr));
}
__device__ __forceinline__ void mma_bf16(float* d, const uint32_t* a, uint32_t b0, uint32_t b1) {
    asm volatile("mma.sync.aligned.m16n8k16.row.col.f32.bf16.bf16.f32 "
        "{%0,%1,%2,%3}, {%4,%5,%6,%7}, {%8,%9}, {%0,%1,%2,%3};"
        : "+f"(d[0]), "+f"(d[1]), "+f"(d[2]), "+f"(d[3])
        : "r"(a[0]), "r"(a[1]), "r"(a[2]), "r"(a[3]), "r"(b0), "r"(b1));
}
__device__ __forceinline__ uint32_t split_pack_hi(float2 f) {
    __nv_bfloat162 h;
    h.x = __float2bfloat16_rn(f.x); h.y = __float2bfloat16_rn(f.y);
    return *(uint32_t*)&h;
}
__device__ __forceinline__ uint32_t split_pack_lo(float2 f) {
    __nv_bfloat16 hx = __float2bfloat16_rn(f.x), hy = __float2bfloat16_rn(f.y);
    __nv_bfloat162 l;
    l.x = __float2bfloat16_rn(f.x - __bfloat162float(hx));
    l.y = __float2bfloat16_rn(f.y - __bfloat162float(hy));
    return *(uint32_t*)&l;
}
__device__ __forceinline__ void cpa16(uint32_t saddr, const void* g) {
    asm volatile("cp.async.cg.shared.global [%0], [%1], 16;" :: "r"(saddr), "l"(g));
}
#define CP_COMMIT() asm volatile("cp.async.commit_group;" ::: "memory")
#define CP_WAIT(n)  asm volatile("cp.async.wait_group %0;" :: "n"(n) : "memory")

#define PSTR 20
#define PTILE (128 * PSTR * 4)    // 10240 B
#define PSMEM (8 * PTILE)         // 81920 B -> 2 CTAs/SM
#define SSTR 36
#define STILE (128 * SSTR * 4)    // 18432 B
#define SSMEM (4 * STILE)         // 73728 B -> 2 CTAs/SM

// ---------------- merged weight/emb build ----------------
#define BLD_W1   (128 * 448)
#define BLD_W2   (BLD_W1 + 128 * 448)
#define BLD_SW   (BLD_W2 + 128 * 256)
#define BLD_EMB  (BLD_SW + N_NODES * 32)
__global__ void k_build_all(const float* __restrict__ basis1, const float* __restrict__ comp1,
                            const float* __restrict__ root1,
                            const float* __restrict__ basis2, const float* __restrict__ comp2,
                            const float* __restrict__ root2,
                            const float* __restrict__ sw1, const float* __restrict__ X) {
    int gid = blockIdx.x * blockDim.x + threadIdx.x;
    if (gid >= BLD_EMB) return;
    if (gid < BLD_W2) {
        const float* basis = (gid < BLD_W1) ? basis1 : basis2;
        const float* comp  = (gid < BLD_W1) ? comp1 : comp2;
        const float* root  = (gid < BLD_W1) ? root1 : root2;
        uint32_t* dh = (gid < BLD_W1) ? g_BT1h : g_BT2h;
        uint32_t* dl = (gid < BLD_W1) ? g_BT1l : g_BT2l;
        int idx = (gid < BLD_W1) ? gid : gid - BLD_W1;
        int o = idx / 448, j = idx % 448, k0 = j * 2;
        float w0, w1;
        if (k0 < 768) {
            int r = k0 >> 7, d0 = k0 & 127;
            w0 = 0.f; w1 = 0.f;
            #pragma unroll
            for (int b = 0; b < NB; b++) {
                float cc = comp[r * NB + b];
                w0 += cc * basis[b * 16384 + d0 * 128 + o];
                w1 += cc * basis[b * 16384 + (d0 + 1) * 128 + o];
            }
        } else {
            int d0 = k0 - 768;
            w0 = root[d0 * 128 + o]; w1 = root[(d0 + 1) * 128 + o];
        }
        float2 f = make_float2(w0, w1);
        dh[idx] = split_pack_hi(f);
        dl[idx] = split_pack_lo(f);
    } else if (gid < BLD_SW) {
        int idx = gid - BLD_W2;
        int o = idx >> 8, j = idx & 255, k0 = j * 2;
        float2 f = make_float2(sw1[k0 * 128 + o], sw1[(k0 + 1) * 128 + o]);
        g_SW1h[idx] = split_pack_hi(f);
        g_SW1l[idx] = split_pack_lo(f);
    } else {
        int idx = gid - BLD_SW;
        float4 f = ((const float4*)X)[idx];
        float2 f01 = make_float2(f.x, f.y), f23 = make_float2(f.z, f.w);
        *(uint2*)(g_Eh + (size_t)idx * 2) = make_uint2(split_pack_hi(f01), split_pack_hi(f23));
        *(uint2*)(g_El + (size_t)idx * 2) = make_uint2(split_pack_lo(f01), split_pack_lo(f23));
    }
}

// ---------------- CSR build ----------------
__global__ void k_count(const int* __restrict__ ei, const int* __restrict__ et) {
    int e = blockIdx.x * blockDim.x + threadIdx.x;
    if (e < NE) atomicAdd(&g_cnt[ei[NE + e] * NREL + et[e]], 1);
}
__global__ __launch_bounds__(SCAN_BLK) void k_scan_a() {
    __shared__ int sm[SCAN_BLK];
    int t = threadIdx.x;
    int gid = blockIdx.x * SCAN_BLK + t;
    int v = (gid < NSEG1) ? g_cnt[gid] : 0;
    sm[t] = v;
    __syncthreads();
    for (int d = 1; d < SCAN_BLK; d <<= 1) {
        int x = (t >= d) ? sm[t - d] : 0;
        __syncthreads();
        sm[t] += x;
        __syncthreads();
    }
    if (gid < NSEG1) g_off[gid] = sm[t] - v;
    if (t == SCAN_BLK - 1) g_bsum[blockIdx.x] = sm[t];
}
__global__ __launch_bounds__(SCAN_BLK) void k_scan_c() {
    __shared__ int red[SCAN_BLK];
    int t = threadIdx.x;
    red[t] = (t < (int)blockIdx.x && t < NBLK) ? g_bsum[t] : 0;
    __syncthreads();
    for (int d = SCAN_BLK / 2; d > 0; d >>= 1) {
        if (t < d) red[t] += red[t + d];
        __syncthreads();
    }
    int pre = red[0];
    int gid = blockIdx.x * SCAN_BLK + t;
    if (gid < NSEG1) {
        int o = g_off[gid] + pre;
        g_off[gid] = o;
        g_cursor[gid] = o;
    }
    if (gid == 0) g_off[NSEG1] = NE;
}
__global__ void k_fill(const int* __restrict__ ei, const int* __restrict__ et) {
    int e = blockIdx.x * blockDim.x + threadIdx.x;
    if (e < NE) {
        int seg = ei[NE + e] * NREL + et[e];
        int pos = atomicAdd(&g_cursor[seg], 1);
        g_esrc[pos] = ei[e];
    }
}

// ---------------- gathers (seg-range parameterized) ----------------
__global__ __launch_bounds__(256) void k_gather1(const float* __restrict__ X, int seg0, int nseg) {
    int w = (int)((blockIdx.x * 256u + threadIdx.x) >> 5);
    if (w >= nseg) return;
    w += seg0;
    int lane = threadIdx.x & 31;
    int s0 = g_off[w], s1 = g_off[w + 1];
    float4 acc = make_float4(0.f, 0.f, 0.f, 0.f);
    for (int e = s0; e < s1; e++) {
        const float4 v = *(const float4*)(X + (size_t)g_esrc[e] * DIM + lane * 4);
        acc.x += v.x; acc.y += v.y; acc.z += v.z; acc.w += v.w;
    }
    float sc = (s1 > s0) ? 1.f / (float)(s1 - s0) : 0.f;
    float2 f01 = make_float2(acc.x * sc, acc.y * sc);
    float2 f23 = make_float2(acc.z * sc, acc.w * sc);
    size_t base = (size_t)w * 64 + lane * 2;
    *(uint2*)(g_A1h + base) = make_uint2(split_pack_hi(f01), split_pack_hi(f23));
    *(uint2*)(g_A1l + base) = make_uint2(split_pack_lo(f01), split_pack_lo(f23));
}
__global__ __launch_bounds__(256) void k_gather2(int seg0, int nseg) {
    int w = (int)((blockIdx.x * 256u + threadIdx.x) >> 5);
    if (w >= nseg) return;
    w += seg0;
    int lane = threadIdx.x & 31;
    int s0 = g_off[w], s1 = g_off[w + 1];
    float4 acc = make_float4(0.f, 0.f, 0.f, 0.f);
    for (int e = s0; e < s1; e++) {
        const float4 v = *(const float4*)(g_x1 + (size_t)g_esrc[e] * DIM + lane * 4);
        acc.x += v.x; acc.y += v.y; acc.z += v.z; acc.w += v.w;
    }
    float sc = (s1 > s0) ? 1.f / (float)(s1 - s0) : 0.f;
    float2 f01 = make_float2(acc.x * sc, acc.y * sc);
    float2 f23 = make_float2(acc.z * sc, acc.w * sc);
    size_t base = (size_t)w * 64 + lane * 2;
    *(uint2*)(g_A2h + base) = make_uint2(split_pack_hi(f01), split_pack_hi(f23));
    *(uint2*)(g_A2l + base) = make_uint2(split_pack_lo(f01), split_pack_lo(f23));
}

// ---------------- pipelined HMMA GEMM core ----------------
#define STAGE_CHUNK(c_, s_, AGGH, AGGL, ROOTH, ROOTL, BTH, BTL, NLIM)                         \
    do {                                                                                      \
        int cc = (c_);                                                                        \
        uint32_t sb0 = sbase + (uint32_t)((s_) * 4) * PTILE;                                  \
        _Pragma("unroll")                                                                     \
        for (int k = 0; k < 2; k++) {                                                         \
            int idx = tid + k * 256;                                                          \
            int row = idx >> 2, c16 = idx & 3;                                                \
            int grow = m0 + row; if (grow >= (NLIM)) grow = (NLIM) - 1;                       \
            const uint32_t *srch, *srcl;                                                      \
            if (cc < 24) {                                                                    \
                size_t sgb = ((size_t)grow * 6 + (cc >> 2)) * 64 + (cc & 3) * 16;             \
                srch = (AGGH) + sgb; srcl = (AGGL) + sgb;                                     \
            } else {                                                                          \
                size_t sgb = (size_t)grow * 64 + (cc - 24) * 16;                              \
                srch = (ROOTH) + sgb; srcl = (ROOTL) + sgb;                                   \
            }                                                                                 \
            uint32_t so = (uint32_t)(row * 80 + c16 * 16);                                    \
            cpa16(sb0 + 0 * PTILE + so, srch + c16 * 4);                                      \
            cpa16(sb0 + 1 * PTILE + so, srcl + c16 * 4);                                      \
            const uint32_t* bh = (BTH) + (size_t)row * 448 + cc * 16;                         \
            const uint32_t* bl = (BTL) + (size_t)row * 448 + cc * 16;                         \
            cpa16(sb0 + 2 * PTILE + so, bh + c16 * 4);                                        \
            cpa16(sb0 + 3 * PTILE + so, bl + c16 * 4);                                        \
        }                                                                                     \
        CP_COMMIT();                                                                          \
    } while (0)

#define MMA_CHUNK(s_)                                                                         \
    do {                                                                                      \
        uint32_t sb0 = sbase + (uint32_t)((s_) * 4) * PTILE;                                  \
        _Pragma("unroll")                                                                     \
        for (int kk = 0; kk < 2; kk++) {                                                      \
            uint32_t ah[2][4], al[2][4], bh[4][4], bl[4][4];                                  \
            _Pragma("unroll")                                                                 \
            for (int mt = 0; mt < 2; mt++) {                                                  \
                uint32_t off = (uint32_t)((wm * 32 + mt * 16 + lrow) * 80 + kk * 32 + lk * 16); \
                ldm4(ah[mt], sb0 + 0 * PTILE + off);                                          \
                ldm4(al[mt], sb0 + 1 * PTILE + off);                                          \
            }                                                                                 \
            _Pragma("unroll")                                                                 \
            for (int nt = 0; nt < 4; nt++) {                                                  \
                uint32_t off = (uint32_t)((wn * 64 + nt * 16 + lrow) * 80 + kk * 32 + lk * 16); \
                ldm4(bh[nt], sb0 + 2 * PTILE + off);                                          \
                ldm4(bl[nt], sb0 + 3 * PTILE + off);                                          \
            }                                                                                 \
            _Pragma("unroll")                                                                 \
            for (int mt = 0; mt < 2; mt++)                                                    \
                _Pragma("unroll")                                                             \
                for (int nt = 0; nt < 4; nt++) {                                              \
                    mma_bf16(acc[mt][2 * nt],     ah[mt], bh[nt][0], bh[nt][2]);              \
                    mma_bf16(acc[mt][2 * nt + 1], ah[mt], bh[nt][1], bh[nt][3]);              \
                    mma_bf16(acc[mt][2 * nt],     al[mt], bh[nt][0], bh[nt][2]);              \
                    mma_bf16(acc[mt][2 * nt + 1], al[mt], bh[nt][1], bh[nt][3]);              \
                    mma_bf16(acc[mt][2 * nt],     ah[mt], bl[nt][0], bl[nt][2]);              \
                    mma_bf16(acc[mt][2 * nt + 1], ah[mt], bl[nt][1], bl[nt][3]);              \
                }                                                                             \
        }                                                                                     \
    } while (0)

// GEMM1 (row_base parameterized)
__global__ __launch_bounds__(256, 2) void k_gemm1_p(const float* __restrict__ bias1, int row_base) {
    extern __shared__ char sm[];
    const uint32_t sbase = smem_u32(sm);
    const int tid = threadIdx.x, lane = tid & 31, wid = tid >> 5;
    const int wm = wid & 3, wn = wid >> 2;
    const int lrow = lane & 15, lk = lane >> 4;
    const int m0 = row_base + blockIdx.x * 128;

    float acc[2][8][4];
    #pragma unroll
    for (int i = 0; i < 2; i++)
        #pragma unroll
        for (int j = 0; j < 8; j++)
            #pragma unroll
            for (int c = 0; c < 4; c++) acc[i][j][c] = 0.f;

    STAGE_CHUNK(0, 0, g_A1h, g_A1l, g_Eh, g_El, g_BT1h, g_BT1l, N_NODES);
    for (int c = 0; c < 28; c++) {
        int s = c & 1;
        if (c < 27) {
            STAGE_CHUNK(c + 1, s ^ 1, g_A1h, g_A1l, g_Eh, g_El, g_BT1h, g_BT1l, N_NODES);
            CP_WAIT(1);
        } else {
            CP_WAIT(0);
        }
        __syncthreads();
        MMA_CHUNK(s);
        __syncthreads();
    }

    const int g = lane >> 2, tc = lane & 3;
    #pragma unroll
    for (int mt = 0; mt < 2; mt++) {
        #pragma unroll
        for (int nb = 0; nb < 8; nb++) {
            int col = wn * 64 + nb * 8 + tc * 2;
            float b0 = bias1[col], b1 = bias1[col + 1];
            int pi = col >> 1;
            int r0 = m0 + wm * 32 + mt * 16 + g;
            if (r0 < N_NODES) {
                float2 v = make_float2(fmaxf(acc[mt][nb][0] + b0, 0.f), fmaxf(acc[mt][nb][1] + b1, 0.f));
                *(float2*)(g_x1 + (size_t)r0 * DIM + col) = v;
                if (r0 < NOUT2) {
                    g_X1h[(size_t)r0 * 64 + pi] = split_pack_hi(v);
                    g_X1l[(size_t)r0 * 64 + pi] = split_pack_lo(v);
                }
            }
            int r1 = r0 + 8;
            if (r1 < N_NODES) {
                float2 v = make_float2(fmaxf(acc[mt][nb][2] + b0, 0.f), fmaxf(acc[mt][nb][3] + b1, 0.f));
                *(float2*)(g_x1 + (size_t)r1 * DIM + col) = v;
                if (r1 < NOUT2) {
                    g_X1h[(size_t)r1 * 64 + pi] = split_pack_hi(v);
                    g_X1l[(size_t)r1 * 64 + pi] = split_pack_lo(v);
                }
            }
        }
    }
}

// GEMM2 (row_base parameterized)
__global__ __launch_bounds__(256, 2) void k_gemm2_p(const float* __restrict__ bias2, int row_base) {
    extern __shared__ char sm[];
    const uint32_t sbase = smem_u32(sm);
    const int tid = threadIdx.x, lane = tid & 31, wid = tid >> 5;
    const int wm = wid & 3, wn = wid >> 2;
    const int lrow = lane & 15, lk = lane >> 4;
    const int m0 = row_base + blockIdx.x * 128;

    float acc[2][8][4];
    #pragma unroll
    for (int i = 0; i < 2; i++)
        #pragma unroll
        for (int j = 0; j < 8; j++)
            #pragma unroll
            for (int c = 0; c < 4; c++) acc[i][j][c] = 0.f;

    STAGE_CHUNK(0, 0, g_A2h, g_A2l, g_X1h, g_X1l, g_BT2h, g_BT2l, NOUT2);
    for (int c = 0; c < 28; c++) {
        int s = c & 1;
        if (c < 27) {
            STAGE_CHUNK(c + 1, s ^ 1, g_A2h, g_A2l, g_X1h, g_X1l, g_BT2h, g_BT2l, NOUT2);
            CP_WAIT(1);
        } else {
            CP_WAIT(0);
        }
        __syncthreads();
        MMA_CHUNK(s);
        __syncthreads();
    }

    const int g = lane >> 2, tc = lane & 3;
    #pragma unroll
    for (int mt = 0; mt < 2; mt++) {
        #pragma unroll
        for (int nb = 0; nb < 8; nb++) {
            int col = wn * 64 + nb * 8 + tc * 2;
            float b0 = bias2[col], b1 = bias2[col + 1];
            int r0 = m0 + wm * 32 + mt * 16 + g;
            if (r0 < NOUT2)
                *(float2*)(g_x2 + (size_t)r0 * DIM + col) =
                    make_float2(acc[mt][nb][0] + b0, acc[mt][nb][1] + b1);
            int r1 = r0 + 8;
            if (r1 < NOUT2)
                *(float2*)(g_x2 + (size_t)r1 * DIM + col) =
                    make_float2(acc[mt][nb][2] + b0, acc[mt][nb][3] + b1);
        }
    }
}

// ---------------- scorer (HMMA): K=64 chunks, 2 CTAs/SM ----------------
__global__ __launch_bounds__(256, 2) void k_scorer_mma(const int* __restrict__ h_idx, const int* __restrict__ p_idx,
                                                       const float* __restrict__ sb1, const float* __restrict__ sw2,
                                                       const float* __restrict__ sb2, float* __restrict__ out) {
    extern __shared__ char sm[];
    __shared__ int sh_h[128], sh_p[128];
    uint32_t* Ah = (uint32_t*)sm;
    uint32_t* Al = (uint32_t*)(sm + STILE);
    const uint32_t sAh = smem_u32(sm), sAl = sAh + STILE, sBh = sAh + 2 * STILE, sBl = sAh + 3 * STILE;
    const int tid = threadIdx.x, lane = tid & 31, wid = tid >> 5;
    const int wm = wid & 3, wn = wid >> 2;
    const int lrow = lane & 15, lk = lane >> 4;
    const int pair0 = blockIdx.x * 128;

    for (int i = tid; i < 128; i += 256) {
        int pr = pair0 + i; if (pr >= NP) pr = NP - 1;
        sh_h[i] = h_idx[pr];
        sh_p[i] = N_HERB + p_idx[pr];
    }
    __syncthreads();

    float acc[2][8][4];
    #pragma unroll
    for (int i = 0; i < 2; i++)
        #pragma unroll
        for (int j = 0; j < 8; j++)
            #pragma unroll
            for (int c = 0; c < 4; c++) acc[i][j][c] = 0.f;

    for (int c = 0; c < 8; c++) {
        for (int i = tid; i < 1024; i += 256) {
            int row = i >> 3, c16 = i & 7;
            uint32_t so = (uint32_t)(row * 144 + c16 * 16);
            cpa16(sBh + so, g_SW1h + (size_t)row * 256 + c * 32 + c16 * 4);
            cpa16(sBl + so, g_SW1l + (size_t)row * 256 + c * 32 + c16 * 4);
        }
        CP_COMMIT();
        for (int i = tid; i < 128 * 32; i += 256) {
            int row = i >> 5, k2 = i & 31;
            int pi = ((c & 1) << 5) + k2;
            const float2* hr = (const float2*)(g_x2 + (size_t)sh_h[row] * DIM);
            const float2* pr = (const float2*)(g_x2 + (size_t)sh_p[row] * DIM);
            float2 f;
            if (c < 2)      f = hr[pi];
            else if (c < 4) f = pr[pi];
            else if (c < 6) { float2 h = hr[pi], p = pr[pi]; f = make_float2(h.x * p.x, h.y * p.y); }
            else            { float2 h = hr[pi], p = pr[pi]; f = make_float2(fabsf(h.x - p.x), fabsf(h.y - p.y)); }
            Ah[row * SSTR + k2] = split_pack_hi(f);
            Al[row * SSTR + k2] = split_pack_lo(f);
        }
        CP_WAIT(0);
        __syncthreads();
        #pragma unroll
        for (int kk = 0; kk < 4; kk++) {
            uint32_t ah[2][4], al[2][4], bh[4][4], bl[4][4];
            #pragma unroll
            for (int mt = 0; mt < 2; mt++) {
                uint32_t off = (uint32_t)((wm * 32 + mt * 16 + lrow) * 144 + kk * 32 + lk * 16);
                ldm4(ah[mt], sAh + off);
                ldm4(al[mt], sAl + off);
            }
            #pragma unroll
            for (int nt = 0; nt < 4; nt++) {
                uint32_t off = (uint32_t)((wn * 64 + nt * 16 + lrow) * 144 + kk * 32 + lk * 16);
                ldm4(bh[nt], sBh + off);
                ldm4(bl[nt], sBl + off);
            }
            #pragma unroll
            for (int mt = 0; mt < 2; mt++)
                #pragma unroll
                for (int nt = 0; nt < 4; nt++) {
                    mma_bf16(acc[mt][2 * nt],     ah[mt], bh[nt][0], bh[nt][2]);
                    mma_bf16(acc[mt][2 * nt + 1], ah[mt], bh[nt][1], bh[nt][3]);
                    mma_bf16(acc[mt][2 * nt],     al[mt], bh[nt][0], bh[nt][2]);
                    mma_bf16(acc[mt][2 * nt + 1], al[mt], bh[nt][1], bh[nt][3]);
                    mma_bf16(acc[mt][2 * nt],     ah[mt], bl[nt][0], bl[nt][2]);
                    mma_bf16(acc[mt][2 * nt + 1], ah[mt], bl[nt][1], bl[nt][3]);
                }
        }
        __syncthreads();
    }

    __syncthreads();
    float* s_part = (float*)sm;
    const int g = lane >> 2, tc = lane & 3;
    #pragma unroll
    for (int mt = 0; mt < 2; mt++) {
        float s0 = 0.f, s1 = 0.f;
        #pragma unroll
        for (int nb = 0; nb < 8; nb++) {
            int col = wn * 64 + nb * 8 + tc * 2;
            float w0 = sw2[col], w1 = sw2[col + 1];
            float bb0 = sb1[col], bb1 = sb1[col + 1];
            s0 += fmaxf(acc[mt][nb][0] + bb0, 0.f) * w0 + fmaxf(acc[mt][nb][1] + bb1, 0.f) * w1;
            s1 += fmaxf(acc[mt][nb][2] + bb0, 0.f) * w0 + fmaxf(acc[mt][nb][3] + bb1, 0.f) * w1;
        }
        s0 += __shfl_xor_sync(0xffffffff, s0, 1); s0 += __shfl_xor_sync(0xffffffff, s0, 2);
        s1 += __shfl_xor_sync(0xffffffff, s1, 1); s1 += __shfl_xor_sync(0xffffffff, s1, 2);
        if (tc == 0) {
            int r0 = wm * 32 + mt * 16 + g;
            s_part[r0 * 2 + wn] = s0;
            s_part[(r0 + 8) * 2 + wn] = s1;
        }
    }
    __syncthreads();
    if (tid < 128) {
        int pr = pair0 + tid;
        if (pr < NP) out[pr] = s_part[tid * 2] + s_part[tid * 2 + 1] + sb2[0];
    }
}

// ---------------- launch ----------------
extern "C" void kernel_launch(void* const* d_in, const int* in_sizes, int n_in,
                              void* d_out, int out_size) {
    const int*   edge_index = (const int*)d_in[0];
    const int*   edge_type  = (const int*)d_in[1];
    const int*   h_idx      = (const int*)d_in[2];
    const int*   p_idx      = (const int*)d_in[3];
    const float* node_emb   = (const float*)d_in[4];
    const float* basis1 = (const float*)d_in[5];
    const float* comp1  = (const float*)d_in[6];
    const float* root1  = (const float*)d_in[7];
    const float* bias1  = (const float*)d_in[8];
    const float* basis2 = (const float*)d_in[9];
    const float* comp2  = (const float*)d_in[10];
    const float* root2  = (const float*)d_in[11];
    const float* bias2  = (const float*)d_in[12];
    const float* sw1 = (const float*)d_in[13];
    const float* sb1 = (const float*)d_in[14];
    const float* sw2 = (const float*)d_in[15];
    const float* sb2 = (const float*)d_in[16];
    float* out = (float*)d_out;

    cudaFuncSetAttribute(k_gemm1_p, cudaFuncAttributeMaxDynamicSharedMemorySize, PSMEM);
    cudaFuncSetAttribute(k_gemm2_p, cudaFuncAttributeMaxDynamicSharedMemorySize, PSMEM);
    cudaFuncSetAttribute(k_scorer_mma, cudaFuncAttributeMaxDynamicSharedMemorySize, SSMEM);

    static cudaStream_t s1 = nullptr;
    static cudaEvent_t evFork = nullptr, evG1A = nullptr, evM1A = nullptr,
                       evG2A = nullptr, evM2A = nullptr, evBuild = nullptr;
    if (s1 == nullptr) {
        cudaStreamCreateWithFlags(&s1, cudaStreamNonBlocking);
        cudaEventCreateWithFlags(&evFork, cudaEventDisableTiming);
        cudaEventCreateWithFlags(&evBuild, cudaEventDisableTiming);
        cudaEventCreateWithFlags(&evG1A, cudaEventDisableTiming);
        cudaEventCreateWithFlags(&evM1A, cudaEventDisableTiming);
        cudaEventCreateWithFlags(&evG2A, cudaEventDisableTiming);
        cudaEventCreateWithFlags(&evM2A, cudaEventDisableTiming);
    }

    // fork: builds on s1
    cudaEventRecord(evFork, 0);
    cudaStreamWaitEvent(s1, evFork, 0);
    k_build_all<<<(BLD_EMB + 255) / 256, 256, 0, s1>>>(basis1, comp1, root1,
                                                       basis2, comp2, root2,
                                                       sw1, node_emb);
    cudaEventRecord(evBuild, s1);

    // main: CSR
    int* cnt_ptr = nullptr;
    cudaGetSymbolAddress((void**)&cnt_ptr, g_cnt);
    cudaMemsetAsync(cnt_ptr, 0, NSEG1 * sizeof(int), 0);
    k_count<<<(NE + 255) / 256, 256>>>(edge_index, edge_type);
    k_scan_a<<<NBLK, SCAN_BLK>>>();
    k_scan_c<<<NBLK, SCAN_BLK>>>();
    k_fill<<<(NE + 255) / 256, 256>>>(edge_index, edge_type);

    // gather1a on main; gemm1a (s1) overlaps gather1b (main)
    k_gather1<<<(S1A * 32 + 255) / 256, 256>>>(node_emb, 0, S1A);
    cudaEventRecord(evG1A, 0);

    cudaStreamWaitEvent(s1, evG1A, 0);                       // s1: build done (in-order) + g1a
    k_gemm1_p<<<G1_BLKA, 256, PSMEM, s1>>>(bias1, 0);
    cudaEventRecord(evM1A, s1);

    k_gather1<<<((NSEG1 - S1A) * 32 + 255) / 256, 256>>>(node_emb, S1A, NSEG1 - S1A);
    cudaStreamWaitEvent(0, evBuild, 0);
    k_gemm1_p<<<G1_BLKB, 256, PSMEM>>>(bias1, R1SPLIT);
    cudaStreamWaitEvent(0, evM1A, 0);                        // x1 fully written

    // gather2a on main; gemm2a (s1) overlaps gather2b (main)
    k_gather2<<<(S2A * 32 + 255) / 256, 256>>>(0, S2A);
    cudaEventRecord(evG2A, 0);

    cudaStreamWaitEvent(s1, evG2A, 0);
    k_gemm2_p<<<G2_BLKA, 256, PSMEM, s1>>>(bias2, 0);
    cudaEventRecord(evM2A, s1);

    k_gather2<<<((NSEG2 - S2A) * 32 + 255) / 256, 256>>>(S2A, NSEG2 - S2A);
    k_gemm2_p<<<G2_BLKB, 256, PSMEM>>>(bias2, R2SPLIT);
    cudaStreamWaitEvent(0, evM2A, 0);                        // x2 fully written

    k_scorer_mma<<<(NP + 127) / 128, 256, SSMEM>>>(h_idx, p_idx, sb1, sw2, sb2, out);
}